// round 6
// baseline (speedup 1.0000x reference)
#include <cuda_runtime.h>
#include <cuda_bf16.h>
#include <cstdint>
#include <math.h>

// Problem constants (fixed by the dataset)
#define NNODES 102400
#define NEDGES 409600
#define HC 256
#define NH 4

// ======================= small helpers =====================================
__device__ __forceinline__ uint32_t smem_to_u32(const void* p) {
    uint32_t a;
    asm("{ .reg .u64 t; cvta.to.shared.u64 t, %1; cvt.u32.u64 %0, t; }" : "=r"(a) : "l"(p));
    return a;
}
__device__ __forceinline__ void cp16(uint32_t s, const void* g) {
    asm volatile("cp.async.cg.shared.global [%0], [%1], 16;" :: "r"(s), "l"(g));
}
__device__ __forceinline__ uint32_t lds32(uint32_t a) {
    uint32_t v; asm volatile("ld.shared.b32 %0, [%1];" : "=r"(v) : "r"(a)); return v;
}
__device__ __forceinline__ uint32_t smaddr(uint32_t base, int r, int c) {
    return base + r * 128 + ((((c >> 2) ^ (r & 7)) << 4)) + ((c & 3) << 2);
}
__device__ __forceinline__ void mma_bf16(float* d, uint32_t a0, uint32_t a1, uint32_t a2,
                                         uint32_t a3, uint32_t b0, uint32_t b1) {
    asm volatile(
        "mma.sync.aligned.m16n8k16.row.col.f32.bf16.bf16.f32 "
        "{%0,%1,%2,%3}, {%4,%5,%6,%7}, {%8,%9}, {%0,%1,%2,%3};"
        : "+f"(d[0]), "+f"(d[1]), "+f"(d[2]), "+f"(d[3])
        : "r"(a0), "r"(a1), "r"(a2), "r"(a3), "r"(b0), "r"(b1));
}
__device__ __forceinline__ float4 leaky4_02(float4 v) {
    v.x = v.x > 0.f ? v.x : 0.2f * v.x;
    v.y = v.y > 0.f ? v.y : 0.2f * v.y;
    v.z = v.z > 0.f ? v.z : 0.2f * v.z;
    v.w = v.w > 0.f ? v.w : 0.2f * v.w;
    return v;
}

// ======================= scratch (device globals) ==========================
__device__ __align__(16) float g_h[(size_t)NNODES * HC];
__device__ __align__(16) float g_als[NNODES * NH];
__device__ __align__(16) float g_ald[NNODES * NH];
__device__ int g_off[NNODES + 1];
__device__ int g_cur[NNODES];
__device__ int g_srcarr[NEDGES];
__device__ int g_is32;
// bf16-split operands
__device__ __align__(16) __nv_bfloat16 g_Ahi[(size_t)NNODES * HC];
__device__ __align__(16) __nv_bfloat16 g_Alo[(size_t)NNODES * HC];
__device__ __align__(16) __nv_bfloat16 g_Bhi[600000];
__device__ __align__(16) __nv_bfloat16 g_Blo[600000];
__device__ __align__(16) __nv_bfloat16 g_rAh[4096 * 64];
__device__ __align__(16) __nv_bfloat16 g_rAl[4096 * 64];
__device__ __align__(16) __nv_bfloat16 g_r1h[4096 * 512];
__device__ __align__(16) __nv_bfloat16 g_r1l[4096 * 512];
__device__ __align__(16) __nv_bfloat16 g_r2h[4096 * 512];
__device__ __align__(16) __nv_bfloat16 g_r2l[4096 * 512];

// B buffer element offsets (B stored [Npad][Kpad], hi/lo, zero padded)
#define OFF_W0  0        // 256 x 128
#define OFF_W1  32768    // 256 x 256
#define OFF_W2  98304    // 256 x 256
#define OFF_FC  163840   // 128 x 256
#define OFF_R1  196608   // 512 x 64
#define OFF_R2  229376   // 512 x 512
#define OFF_R3  491520   // 128 x 512

// ======================= edge utilities ====================================
__device__ __forceinline__ void load_edge(const void* ei, int is32, int idx,
                                          int& src, int& dst) {
    if (is32) {
        src = ((const int*)ei)[idx];
        dst = ((const int*)ei)[NEDGES + idx];
    } else {
        src = (int)((const long long*)ei)[idx];
        dst = (int)((const long long*)ei)[NEDGES + idx];
    }
}

__global__ void detect_idx_kernel(const long long* ei, int* flag) {
    int i = blockIdx.x * blockDim.x + threadIdx.x;
    if (i >= NEDGES) return;
    long long v = ei[i];
    if (v < 0 || v >= (long long)NNODES) atomicOr(flag, 1);
}

__global__ void hist_kernel(const void* __restrict__ ei, const int* __restrict__ flag,
                            int* __restrict__ counts) {
    int i = blockIdx.x * blockDim.x + threadIdx.x;
    if (i >= NEDGES) return;
    int s, d;
    load_edge(ei, *flag, i, s, d);
    atomicAdd(&counts[d], 1);
}

// single block, 1024 threads, 100 counts each (1024*100 == NNODES)
__global__ void scan_kernel(int* __restrict__ counts_cursor, int* __restrict__ offs) {
    __shared__ int part[1024];
    int t = threadIdx.x;
    int base = t * 100;
    int sum = 0;
    for (int i = 0; i < 100; i++) sum += counts_cursor[base + i];
    part[t] = sum;
    __syncthreads();
    for (int d = 1; d < 1024; d <<= 1) {
        int v = (t >= d) ? part[t - d] : 0;
        __syncthreads();
        part[t] += v;
        __syncthreads();
    }
    int run = (t == 0) ? 0 : part[t - 1];
    for (int i = 0; i < 100; i++) {
        int c = counts_cursor[base + i];
        offs[base + i] = run;
        counts_cursor[base + i] = run;   // cursor for scatter
        run += c;
    }
    if (t == 1023) offs[NNODES] = run;
}

__global__ void scatter_kernel(const void* __restrict__ ei, const int* __restrict__ flag,
                               int* __restrict__ cursor, int* __restrict__ srcarr) {
    int i = blockIdx.x * blockDim.x + threadIdx.x;
    if (i >= NEDGES) return;
    int s, d;
    load_edge(ei, *flag, i, s, d);
    int pos = atomicAdd(&cursor[d], 1);
    srcarr[pos] = s;
}

// ======================= misc conversions ==================================
__global__ void conv_A_kernel(const float* __restrict__ A,
                              __nv_bfloat16* __restrict__ hi, __nv_bfloat16* __restrict__ lo,
                              int M, int K, int Kpad) {
    int i = blockIdx.x * blockDim.x + threadIdx.x;
    if (i >= M * Kpad) return;
    int m = i / Kpad, k = i - m * Kpad;
    float v = (k < K) ? A[(size_t)m * K + k] : 0.f;
    __nv_bfloat16 h16 = __float2bfloat16(v);
    hi[i] = h16;
    lo[i] = __float2bfloat16(v - __bfloat162float(h16));
}

__global__ void conv_B_kernel(const float* __restrict__ B,
                              __nv_bfloat16* __restrict__ hi, __nv_bfloat16* __restrict__ lo,
                              int K, int N, int Kpad, int Npad) {
    int i = blockIdx.x * blockDim.x + threadIdx.x;
    if (i >= Npad * Kpad) return;
    int n = i / Kpad, k = i - n * Kpad;
    float v = (k < K && n < N) ? B[(size_t)k * N + n] : 0.f;
    __nv_bfloat16 h16 = __float2bfloat16(v);
    hi[i] = h16;
    lo[i] = __float2bfloat16(v - __bfloat162float(h16));
}

// ======================= bf16-split mma.sync GEMM ==========================
// 256 threads = 8 warps (2 warpM x 4 warpN), warp tile 64 x (N8*8).
// CTA tile 128 x NBLK (NBLK = N8*32). K chunks of 64, double buffered.
template<int N8>
__global__ __launch_bounds__(256, 1)
void gemm_mma(const __nv_bfloat16* __restrict__ Ahi, const __nv_bfloat16* __restrict__ Alo,
              int Kpad,
              const __nv_bfloat16* __restrict__ Bhi, const __nv_bfloat16* __restrict__ Blo,
              float* outf, int nwrite, int ldout,
              __nv_bfloat16* ohi, __nv_bfloat16* olo, int ldo2,
              const float* __restrict__ bias, int act,
              const float* __restrict__ a_src, const float* __restrict__ a_dst,
              float* als, float* ald)
{
    constexpr int NBLK = N8 * 32;
    constexpr uint32_t BSTAGE = (uint32_t)NBLK * 128u;   // bytes per B half
    constexpr uint32_t STAGE = 32768u + 2u * BSTAGE;
    extern __shared__ char sm_raw[];
    uint32_t sb = smem_to_u32(sm_raw);
    int tid = threadIdx.x, wid = tid >> 5, lane = tid & 31;
    int warpM = wid & 1, warpN = wid >> 1;
    int mBase = blockIdx.x * 128;
    int nBase = blockIdx.y * NBLK;
    const int NC = Kpad >> 6;
    const int kp = lane & 3;
    const int lq = lane >> 2;

    float acc[4][N8][4];
#pragma unroll
    for (int i = 0; i < 4; i++)
#pragma unroll
        for (int j = 0; j < N8; j++)
#pragma unroll
            for (int q = 0; q < 4; q++) acc[i][j][q] = 0.f;

    // ---- prologue: stage 0 ----
    {
        uint32_t base = sb;
#pragma unroll
        for (int i = 0; i < 8; i++) {                 // A: 2048 granules
            int u = tid + i * 256;
            int hl = u >> 10, rem = u & 1023, row = rem >> 3, g = rem & 7;
            const __nv_bfloat16* src = (hl ? Alo : Ahi) + (size_t)(mBase + row) * Kpad + g * 8;
            cp16(base + hl * 16384 + row * 128 + (((g ^ (row & 7)) << 4)), src);
        }
#pragma unroll
        for (int i = 0; i < N8 * 2; i++) {            // B: NBLK*16 granules
            int u = tid + i * 256;
            int hl = (u >= NBLK * 8);
            int rem = u - hl * NBLK * 8;
            int row = rem >> 3, g = rem & 7;
            const __nv_bfloat16* src = (hl ? Blo : Bhi) + (size_t)(nBase + row) * Kpad + g * 8;
            cp16(base + 32768 + hl * BSTAGE + row * 128 + (((g ^ (row & 7)) << 4)), src);
        }
        asm volatile("cp.async.commit_group;" ::: "memory");
    }

    for (int c = 0; c < NC; c++) {
        if (c + 1 < NC) {
            uint32_t base = sb + ((c + 1) & 1) * STAGE;
            int ko = (c + 1) * 64;
#pragma unroll
            for (int i = 0; i < 8; i++) {
                int u = tid + i * 256;
                int hl = u >> 10, rem = u & 1023, row = rem >> 3, g = rem & 7;
                const __nv_bfloat16* src = (hl ? Alo : Ahi) + (size_t)(mBase + row) * Kpad + ko + g * 8;
                cp16(base + hl * 16384 + row * 128 + (((g ^ (row & 7)) << 4)), src);
            }
#pragma unroll
            for (int i = 0; i < N8 * 2; i++) {
                int u = tid + i * 256;
                int hl = (u >= NBLK * 8);
                int rem = u - hl * NBLK * 8;
                int row = rem >> 3, g = rem & 7;
                const __nv_bfloat16* src = (hl ? Blo : Bhi) + (size_t)(nBase + row) * Kpad + ko + g * 8;
                cp16(base + 32768 + hl * BSTAGE + row * 128 + (((g ^ (row & 7)) << 4)), src);
            }
            asm volatile("cp.async.commit_group;" ::: "memory");
            asm volatile("cp.async.wait_group 1;" ::: "memory");
        } else {
            asm volatile("cp.async.wait_group 0;" ::: "memory");
        }
        __syncthreads();

        uint32_t aB = sb + (c & 1) * STAGE;
        uint32_t bB = aB + 32768;
#pragma unroll
        for (int k16 = 0; k16 < 4; k16++) {
            int c0 = k16 * 8;
            uint32_t Ah[4][4], Al[4][4];
#pragma unroll
            for (int mf = 0; mf < 4; mf++) {
                int r0 = warpM * 64 + mf * 16 + lq;
                Ah[mf][0] = lds32(smaddr(aB, r0,     c0 + kp));
                Ah[mf][1] = lds32(smaddr(aB, r0 + 8, c0 + kp));
                Ah[mf][2] = lds32(smaddr(aB, r0,     c0 + kp + 4));
                Ah[mf][3] = lds32(smaddr(aB, r0 + 8, c0 + kp + 4));
                Al[mf][0] = lds32(smaddr(aB + 16384, r0,     c0 + kp));
                Al[mf][1] = lds32(smaddr(aB + 16384, r0 + 8, c0 + kp));
                Al[mf][2] = lds32(smaddr(aB + 16384, r0,     c0 + kp + 4));
                Al[mf][3] = lds32(smaddr(aB + 16384, r0 + 8, c0 + kp + 4));
            }
#pragma unroll
            for (int n8 = 0; n8 < N8; n8++) {
                int n = warpN * N8 * 8 + n8 * 8 + lq;
                uint32_t bh0 = lds32(smaddr(bB, n, c0 + kp));
                uint32_t bh1 = lds32(smaddr(bB, n, c0 + kp + 4));
                uint32_t bl0 = lds32(smaddr(bB + BSTAGE, n, c0 + kp));
                uint32_t bl1 = lds32(smaddr(bB + BSTAGE, n, c0 + kp + 4));
#pragma unroll
                for (int mf = 0; mf < 4; mf++) {
                    mma_bf16(acc[mf][n8], Ah[mf][0], Ah[mf][1], Ah[mf][2], Ah[mf][3], bh0, bh1);
                    mma_bf16(acc[mf][n8], Ah[mf][0], Ah[mf][1], Ah[mf][2], Ah[mf][3], bl0, bl1);
                    mma_bf16(acc[mf][n8], Al[mf][0], Al[mf][1], Al[mf][2], Al[mf][3], bh0, bh1);
                }
            }
        }
        __syncthreads();
    }

    // ---- epilogue ----
    int limit = nwrite - nBase;
    float s1[4][2], s2[4][2];
#pragma unroll
    for (int mf = 0; mf < 4; mf++) { s1[mf][0] = s1[mf][1] = 0.f; s2[mf][0] = s2[mf][1] = 0.f; }
#pragma unroll
    for (int mf = 0; mf < 4; mf++) {
        int gr0 = mBase + warpM * 64 + mf * 16 + lq;
#pragma unroll
        for (int n8 = 0; n8 < N8; n8++) {
            int cl = warpN * N8 * 8 + n8 * 8 + kp * 2;
            float v[4];
#pragma unroll
            for (int q = 0; q < 4; q++) v[q] = acc[mf][n8][q];
#pragma unroll
            for (int q = 0; q < 4; q++) {
                int col = cl + (q & 1);
                if (col < limit) {
                    float x = v[q];
                    if (bias) x += bias[nBase + col];
                    if (act) x = x > 0.f ? x : 0.01f * x;
                    v[q] = x;
                }
            }
            if (a_src) {
                s1[mf][0] += v[0] * a_src[cl] + v[1] * a_src[cl + 1];
                s2[mf][0] += v[0] * a_dst[cl] + v[1] * a_dst[cl + 1];
                s1[mf][1] += v[2] * a_src[cl] + v[3] * a_src[cl + 1];
                s2[mf][1] += v[2] * a_dst[cl] + v[3] * a_dst[cl + 1];
            }
            if (outf) {
                if (cl + 1 < limit) {
                    *(float2*)(outf + (size_t)gr0 * ldout + nBase + cl) = make_float2(v[0], v[1]);
                    *(float2*)(outf + (size_t)(gr0 + 8) * ldout + nBase + cl) = make_float2(v[2], v[3]);
                } else if (cl < limit) {
                    outf[(size_t)gr0 * ldout + nBase + cl] = v[0];
                    outf[(size_t)(gr0 + 8) * ldout + nBase + cl] = v[2];
                }
            }
            if (ohi && cl < limit) {
                __nv_bfloat16 h0 = __float2bfloat16(v[0]);
                __nv_bfloat16 h1 = __float2bfloat16(v[1]);
                __nv_bfloat16 l0 = __float2bfloat16(v[0] - __bfloat162float(h0));
                __nv_bfloat16 l1 = __float2bfloat16(v[1] - __bfloat162float(h1));
                *(__nv_bfloat162*)(ohi + (size_t)gr0 * ldo2 + nBase + cl) = __nv_bfloat162(h0, h1);
                *(__nv_bfloat162*)(olo + (size_t)gr0 * ldo2 + nBase + cl) = __nv_bfloat162(l0, l1);
                __nv_bfloat16 h2 = __float2bfloat16(v[2]);
                __nv_bfloat16 h3 = __float2bfloat16(v[3]);
                __nv_bfloat16 l2 = __float2bfloat16(v[2] - __bfloat162float(h2));
                __nv_bfloat16 l3 = __float2bfloat16(v[3] - __bfloat162float(h3));
                *(__nv_bfloat162*)(ohi + (size_t)(gr0 + 8) * ldo2 + nBase + cl) = __nv_bfloat162(h2, h3);
                *(__nv_bfloat162*)(olo + (size_t)(gr0 + 8) * ldo2 + nBase + cl) = __nv_bfloat162(l2, l3);
            }
        }
    }
    if (a_src) {
        // warpN == head (N8 == 8: warp covers 64 cols == one head)
#pragma unroll
        for (int mf = 0; mf < 4; mf++)
#pragma unroll
            for (int hf = 0; hf < 2; hf++) {
                s1[mf][hf] += __shfl_xor_sync(0xFFFFFFFF, s1[mf][hf], 1);
                s1[mf][hf] += __shfl_xor_sync(0xFFFFFFFF, s1[mf][hf], 2);
                s2[mf][hf] += __shfl_xor_sync(0xFFFFFFFF, s2[mf][hf], 1);
                s2[mf][hf] += __shfl_xor_sync(0xFFFFFFFF, s2[mf][hf], 2);
            }
        if ((lane & 3) == 0) {
#pragma unroll
            for (int mf = 0; mf < 4; mf++)
#pragma unroll
                for (int hf = 0; hf < 2; hf++) {
                    int gr = mBase + warpM * 64 + mf * 16 + hf * 8 + lq;
                    als[gr * 4 + warpN] = s1[mf][hf];
                    ald[gr * 4 + warpN] = s2[mf][hf];
                }
        }
    }
}

// ======================= fused GAT aggregation (one warp per dst) ==========
__global__ __launch_bounds__(256)
void gat_agg(const int* __restrict__ offs, const int* __restrict__ srcarr,
             const float4* __restrict__ als4, const float4* __restrict__ ald4,
             const float* __restrict__ h,
             const float* __restrict__ bias, int act,
             __nv_bfloat16* __restrict__ ohi, __nv_bfloat16* __restrict__ olo)
{
    int w = (blockIdx.x * blockDim.x + threadIdx.x) >> 5;
    int lane = threadIdx.x & 31;
    if (w >= NNODES) return;
    int n = w;
    int beg = offs[n], end = offs[n + 1];
    float4 aldn = ald4[n];
    float4 an = als4[n];
    float4 eself = leaky4_02(make_float4(an.x + aldn.x, an.y + aldn.y,
                                         an.z + aldn.z, an.w + aldn.w));
    // ---- pass 1: segment max ----
    float4 m = eself;
    for (int j = beg + lane; j < end; j += 32) {
        int s = srcarr[j];
        float4 a = als4[s];
        float4 e = leaky4_02(make_float4(a.x + aldn.x, a.y + aldn.y,
                                         a.z + aldn.z, a.w + aldn.w));
        m.x = fmaxf(m.x, e.x); m.y = fmaxf(m.y, e.y);
        m.z = fmaxf(m.z, e.z); m.w = fmaxf(m.w, e.w);
    }
#pragma unroll
    for (int o = 16; o; o >>= 1) {
        m.x = fmaxf(m.x, __shfl_xor_sync(0xFFFFFFFF, m.x, o));
        m.y = fmaxf(m.y, __shfl_xor_sync(0xFFFFFFFF, m.y, o));
        m.z = fmaxf(m.z, __shfl_xor_sync(0xFFFFFFFF, m.z, o));
        m.w = fmaxf(m.w, __shfl_xor_sync(0xFFFFFFFF, m.w, o));
    }
    // ---- pass 2: p, sum, gather-accumulate ----
    float acc[8] = {0.f, 0.f, 0.f, 0.f, 0.f, 0.f, 0.f, 0.f};
    float4 psum = make_float4(0.f, 0.f, 0.f, 0.f);
    for (int base = beg; base < end; base += 32) {
        int j = base + lane;
        int valid = j < end;
        int s = valid ? srcarr[j] : 0;
        float4 p = make_float4(0.f, 0.f, 0.f, 0.f);
        if (valid) {
            float4 a = als4[s];
            float4 e = leaky4_02(make_float4(a.x + aldn.x, a.y + aldn.y,
                                             a.z + aldn.z, a.w + aldn.w));
            p.x = __expf(e.x - m.x); p.y = __expf(e.y - m.y);
            p.z = __expf(e.z - m.z); p.w = __expf(e.w - m.w);
            psum.x += p.x; psum.y += p.y; psum.z += p.z; psum.w += p.w;
        }
        int cnt = end - base; if (cnt > 32) cnt = 32;
        for (int jj = 0; jj < cnt; jj++) {
            int   sj = __shfl_sync(0xFFFFFFFF, s, jj);
            float px = __shfl_sync(0xFFFFFFFF, p.x, jj);
            float py = __shfl_sync(0xFFFFFFFF, p.y, jj);
            float pz = __shfl_sync(0xFFFFFFFF, p.z, jj);
            float pw = __shfl_sync(0xFFFFFFFF, p.w, jj);
            const float4* hf = (const float4*)(h + (size_t)sj * HC);
            float pA = (lane < 16) ? px : py;
            float pB = (lane < 16) ? pz : pw;
            float4 vA = __ldg(&hf[lane]);
            float4 vB = __ldg(&hf[lane + 32]);
            acc[0] += pA * vA.x; acc[1] += pA * vA.y;
            acc[2] += pA * vA.z; acc[3] += pA * vA.w;
            acc[4] += pB * vB.x; acc[5] += pB * vB.y;
            acc[6] += pB * vB.z; acc[7] += pB * vB.w;
        }
    }
#pragma unroll
    for (int o = 16; o; o >>= 1) {
        psum.x += __shfl_xor_sync(0xFFFFFFFF, psum.x, o);
        psum.y += __shfl_xor_sync(0xFFFFFFFF, psum.y, o);
        psum.z += __shfl_xor_sync(0xFFFFFFFF, psum.z, o);
        psum.w += __shfl_xor_sync(0xFFFFFFFF, psum.w, o);
    }
    // self loop contribution
    float4 ps;
    ps.x = __expf(eself.x - m.x); ps.y = __expf(eself.y - m.y);
    ps.z = __expf(eself.z - m.z); ps.w = __expf(eself.w - m.w);
    psum.x += ps.x; psum.y += ps.y; psum.z += ps.z; psum.w += ps.w;
    {
        const float4* hf = (const float4*)(h + (size_t)n * HC);
        float pA = (lane < 16) ? ps.x : ps.y;
        float pB = (lane < 16) ? ps.z : ps.w;
        float4 vA = hf[lane];
        float4 vB = hf[lane + 32];
        acc[0] += pA * vA.x; acc[1] += pA * vA.y;
        acc[2] += pA * vA.z; acc[3] += pA * vA.w;
        acc[4] += pB * vB.x; acc[5] += pB * vB.y;
        acc[6] += pB * vB.z; acc[7] += pB * vB.w;
    }
    // ---- epilogue: divide, bias, act, write bf16 hi/lo ----
    float sA = (lane < 16) ? psum.x : psum.y;
    float sB = (lane < 16) ? psum.z : psum.w;
    const float4* b4 = (const float4*)bias;
    float4 bA = b4[lane], bB = b4[lane + 32];
    float v[8];
    float rA = 1.f / sA, rB = 1.f / sB;
    v[0] = acc[0] * rA + bA.x; v[1] = acc[1] * rA + bA.y;
    v[2] = acc[2] * rA + bA.z; v[3] = acc[3] * rA + bA.w;
    v[4] = acc[4] * rB + bB.x; v[5] = acc[5] * rB + bB.y;
    v[6] = acc[6] * rB + bB.z; v[7] = acc[7] * rB + bB.w;
    if (act) {
#pragma unroll
        for (int q = 0; q < 8; q++) v[q] = v[q] > 0.f ? v[q] : 0.01f * v[q];
    }
    size_t i0 = (size_t)n * HC + lane * 4;
    size_t i1 = (size_t)n * HC + (lane + 32) * 4;
#pragma unroll
    for (int g = 0; g < 2; g++) {
        size_t ix = g ? i1 : i0;
        const float* vv = v + g * 4;
        __nv_bfloat16 h0 = __float2bfloat16(vv[0]);
        __nv_bfloat16 h1 = __float2bfloat16(vv[1]);
        __nv_bfloat16 h2 = __float2bfloat16(vv[2]);
        __nv_bfloat16 h3 = __float2bfloat16(vv[3]);
        *(__nv_bfloat162*)(ohi + ix)     = __nv_bfloat162(h0, h1);
        *(__nv_bfloat162*)(ohi + ix + 2) = __nv_bfloat162(h2, h3);
        __nv_bfloat16 l0 = __float2bfloat16(vv[0] - __bfloat162float(h0));
        __nv_bfloat16 l1 = __float2bfloat16(vv[1] - __bfloat162float(h1));
        __nv_bfloat16 l2 = __float2bfloat16(vv[2] - __bfloat162float(h2));
        __nv_bfloat16 l3 = __float2bfloat16(vv[3] - __bfloat162float(h3));
        *(__nv_bfloat162*)(olo + ix)     = __nv_bfloat162(l0, l1);
        *(__nv_bfloat162*)(olo + ix + 2) = __nv_bfloat162(l2, l3);
    }
}

// ======================= host orchestration ================================
#define SMEM_N8  (2 * (32768 + 2 * 256 * 128))   // 196608
#define SMEM_N4  (2 * (32768 + 2 * 128 * 128))   // 131072

extern "C" void kernel_launch(void* const* d_in, const int* in_sizes, int n_in,
                              void* d_out, int out_size)
{
    const float* x    = (const float*)d_in[0];
    const void*  ei   = d_in[1];
    const float* root = (const float*)d_in[2];
    const float* W[3]  = {(const float*)d_in[3], (const float*)d_in[7],  (const float*)d_in[11]};
    const float* aS[3] = {(const float*)d_in[4], (const float*)d_in[8],  (const float*)d_in[12]};
    const float* aD[3] = {(const float*)d_in[5], (const float*)d_in[9],  (const float*)d_in[13]};
    const float* bb[3] = {(const float*)d_in[6], (const float*)d_in[10], (const float*)d_in[14]};
    const float* fc_w = (const float*)d_in[15];
    const float* fc_b = (const float*)d_in[16];
    const float* r_w1 = (const float*)d_in[17];
    const float* r_b1 = (const float*)d_in[18];
    const float* r_w2 = (const float*)d_in[19];
    const float* r_b2 = (const float*)d_in[20];
    const float* r_w3 = (const float*)d_in[21];
    const float* r_b3 = (const float*)d_in[22];

    float *p_h, *p_als, *p_ald;
    int *p_off, *p_cur, *p_srcarr, *p_flag;
    __nv_bfloat16 *p_Ahi, *p_Alo, *p_Bhi, *p_Blo, *p_rAh, *p_rAl, *p_r1h, *p_r1l, *p_r2h, *p_r2l;
    cudaGetSymbolAddress((void**)&p_h,   g_h);
    cudaGetSymbolAddress((void**)&p_als, g_als);
    cudaGetSymbolAddress((void**)&p_ald, g_ald);
    cudaGetSymbolAddress((void**)&p_off, g_off);
    cudaGetSymbolAddress((void**)&p_cur, g_cur);
    cudaGetSymbolAddress((void**)&p_srcarr, g_srcarr);
    cudaGetSymbolAddress((void**)&p_flag, g_is32);
    cudaGetSymbolAddress((void**)&p_Ahi, g_Ahi);
    cudaGetSymbolAddress((void**)&p_Alo, g_Alo);
    cudaGetSymbolAddress((void**)&p_Bhi, g_Bhi);
    cudaGetSymbolAddress((void**)&p_Blo, g_Blo);
    cudaGetSymbolAddress((void**)&p_rAh, g_rAh);
    cudaGetSymbolAddress((void**)&p_rAl, g_rAl);
    cudaGetSymbolAddress((void**)&p_r1h, g_r1h);
    cudaGetSymbolAddress((void**)&p_r1l, g_r1l);
    cudaGetSymbolAddress((void**)&p_r2h, g_r2h);
    cudaGetSymbolAddress((void**)&p_r2l, g_r2l);

    static int smem_set = 0;
    if (!smem_set) {
        cudaFuncSetAttribute(gemm_mma<8>, cudaFuncAttributeMaxDynamicSharedMemorySize, SMEM_N8);
        cudaFuncSetAttribute(gemm_mma<4>, cudaFuncAttributeMaxDynamicSharedMemorySize, SMEM_N4);
        smem_set = 1;
    }

    // ---- CSR build (once per call, reused by all 3 layers) ----
    cudaMemsetAsync(p_flag, 0, sizeof(int));
    detect_idx_kernel<<<(NEDGES + 255) / 256, 256>>>((const long long*)ei, p_flag);
    cudaMemsetAsync(p_cur, 0, NNODES * sizeof(int));
    hist_kernel<<<(NEDGES + 255) / 256, 256>>>(ei, p_flag, p_cur);
    scan_kernel<<<1, 1024>>>(p_cur, p_off);
    scatter_kernel<<<(NEDGES + 255) / 256, 256>>>(ei, p_flag, p_cur, p_srcarr);

    // ---- weight conversions ----
    conv_B_kernel<<<(256 * 128 + 255) / 256, 256>>>(W[0], p_Bhi + OFF_W0, p_Blo + OFF_W0, 80, 256, 128, 256);
    conv_B_kernel<<<(256 * 256 + 255) / 256, 256>>>(W[1], p_Bhi + OFF_W1, p_Blo + OFF_W1, 256, 256, 256, 256);
    conv_B_kernel<<<(256 * 256 + 255) / 256, 256>>>(W[2], p_Bhi + OFF_W2, p_Blo + OFF_W2, 256, 256, 256, 256);
    conv_B_kernel<<<(128 * 256 + 255) / 256, 256>>>(fc_w, p_Bhi + OFF_FC, p_Blo + OFF_FC, 256, 80, 256, 128);
    conv_B_kernel<<<(512 * 64 + 255) / 256, 256>>>(r_w1, p_Bhi + OFF_R1, p_Blo + OFF_R1, 60, 512, 64, 512);
    conv_B_kernel<<<(512 * 512 + 255) / 256, 256>>>(r_w2, p_Bhi + OFF_R2, p_Blo + OFF_R2, 512, 512, 512, 512);
    conv_B_kernel<<<(128 * 512 + 255) / 256, 256>>>(r_w3, p_Bhi + OFF_R3, p_Blo + OFF_R3, 512, 60, 512, 128);

    // x -> bf16 hi/lo, K padded 80->128
    conv_A_kernel<<<(NNODES * 128 + 255) / 256, 256>>>(x, p_Ahi, p_Alo, NNODES, 80, 128);

    const int Kpad[3] = {128, 256, 256};
    const __nv_bfloat16* Boff_hi[3] = {p_Bhi + OFF_W0, p_Bhi + OFF_W1, p_Bhi + OFF_W2};
    const __nv_bfloat16* Boff_lo[3] = {p_Blo + OFF_W0, p_Blo + OFF_W1, p_Blo + OFF_W2};

    for (int L = 0; L < 3; L++) {
        gemm_mma<8><<<dim3(NNODES / 128, 1), 256, SMEM_N8>>>(
            p_Ahi, p_Alo, Kpad[L], Boff_hi[L], Boff_lo[L],
            p_h, 256, 256, nullptr, nullptr, 0,
            nullptr, 0, aS[L], aD[L], p_als, p_ald);
        int act = (L < 2) ? 1 : 0;
        gat_agg<<<NNODES / 8, 256>>>(p_off, p_srcarr,
                                     (const float4*)p_als, (const float4*)p_ald,
                                     p_h, bb[L], act, p_Ahi, p_Alo);
    }

    // rot = h @ fc_w + fc_b -> d_out[0 : N*80]  (NBLK=128, only 80 valid)
    float* rot = (float*)d_out;
    gemm_mma<4><<<dim3(NNODES / 128, 1), 256, SMEM_N4>>>(
        p_Ahi, p_Alo, 256, p_Bhi + OFF_FC, p_Blo + OFF_FC,
        rot, 80, 80, nullptr, nullptr, 0,
        fc_b, 0, nullptr, nullptr, nullptr, nullptr);

    // root MLP
    conv_A_kernel<<<(4096 * 64 + 255) / 256, 256>>>(root, p_rAh, p_rAl, 4096, 60, 64);
    gemm_mma<8><<<dim3(32, 2), 256, SMEM_N8>>>(
        p_rAh, p_rAl, 64, p_Bhi + OFF_R1, p_Blo + OFF_R1,
        nullptr, 512, 0, p_r1h, p_r1l, 512,
        r_b1, 1, nullptr, nullptr, nullptr, nullptr);
    gemm_mma<8><<<dim3(32, 2), 256, SMEM_N8>>>(
        p_r1h, p_r1l, 512, p_Bhi + OFF_R2, p_Blo + OFF_R2,
        nullptr, 512, 0, p_r2h, p_r2l, 512,
        r_b2, 1, nullptr, nullptr, nullptr, nullptr);
    float* root_out = rot + (size_t)NNODES * 80;
    gemm_mma<4><<<dim3(32, 1), 256, SMEM_N4>>>(
        p_r2h, p_r2l, 512, p_Bhi + OFF_R3, p_Blo + OFF_R3,
        root_out, 60, 60, nullptr, nullptr, 0,
        r_b3, 0, nullptr, nullptr, nullptr, nullptr);
}

// round 7
// speedup vs baseline: 1.0776x; 1.0776x over previous
#include <cuda_runtime.h>
#include <cuda_bf16.h>
#include <cstdint>
#include <math.h>

// Problem constants (fixed by the dataset)
#define NNODES 102400
#define NEDGES 409600
#define HC 256
#define NH 4

// ======================= small helpers =====================================
__device__ __forceinline__ uint32_t smem_to_u32(const void* p) {
    uint32_t a;
    asm("{ .reg .u64 t; cvta.to.shared.u64 t, %1; cvt.u32.u64 %0, t; }" : "=r"(a) : "l"(p));
    return a;
}
__device__ __forceinline__ void cp16(uint32_t s, const void* g) {
    asm volatile("cp.async.cg.shared.global [%0], [%1], 16;" :: "r"(s), "l"(g));
}
__device__ __forceinline__ uint32_t lds32(uint32_t a) {
    uint32_t v; asm volatile("ld.shared.b32 %0, [%1];" : "=r"(v) : "r"(a)); return v;
}
__device__ __forceinline__ uint32_t smaddr(uint32_t base, int r, int c) {
    return base + r * 128 + ((((c >> 2) ^ (r & 7)) << 4)) + ((c & 3) << 2);
}
__device__ __forceinline__ void mma_bf16(float* d, uint32_t a0, uint32_t a1, uint32_t a2,
                                         uint32_t a3, uint32_t b0, uint32_t b1) {
    asm volatile(
        "mma.sync.aligned.m16n8k16.row.col.f32.bf16.bf16.f32 "
        "{%0,%1,%2,%3}, {%4,%5,%6,%7}, {%8,%9}, {%0,%1,%2,%3};"
        : "+f"(d[0]), "+f"(d[1]), "+f"(d[2]), "+f"(d[3])
        : "r"(a0), "r"(a1), "r"(a2), "r"(a3), "r"(b0), "r"(b1));
}
__device__ __forceinline__ float4 leaky4_02(float4 v) {
    v.x = v.x > 0.f ? v.x : 0.2f * v.x;
    v.y = v.y > 0.f ? v.y : 0.2f * v.y;
    v.z = v.z > 0.f ? v.z : 0.2f * v.z;
    v.w = v.w > 0.f ? v.w : 0.2f * v.w;
    return v;
}

// ======================= scratch (device globals) ==========================
__device__ __align__(16) float g_h[(size_t)NNODES * HC];
__device__ __align__(16) float g_als[NNODES * NH];
__device__ __align__(16) float g_ald[NNODES * NH];
__device__ int g_off[NNODES + 1];
__device__ int g_cur[NNODES];
__device__ int g_srcarr[NEDGES];
__device__ int g_is32;
// bf16-split operands
__device__ __align__(16) __nv_bfloat16 g_Ahi[(size_t)NNODES * HC];
__device__ __align__(16) __nv_bfloat16 g_Alo[(size_t)NNODES * HC];
__device__ __align__(16) __nv_bfloat16 g_Bhi[600000];
__device__ __align__(16) __nv_bfloat16 g_Blo[600000];
__device__ __align__(16) __nv_bfloat16 g_rAh[4096 * 64];
__device__ __align__(16) __nv_bfloat16 g_rAl[4096 * 64];
__device__ __align__(16) __nv_bfloat16 g_r1h[4096 * 512];
__device__ __align__(16) __nv_bfloat16 g_r1l[4096 * 512];
__device__ __align__(16) __nv_bfloat16 g_r2h[4096 * 512];
__device__ __align__(16) __nv_bfloat16 g_r2l[4096 * 512];

// B buffer element offsets (B stored [Npad][Kpad], hi/lo, zero padded)
#define OFF_W0  0        // 256 x 128
#define OFF_W1  32768    // 256 x 256
#define OFF_W2  98304    // 256 x 256
#define OFF_FC  163840   // 128 x 256
#define OFF_R1  196608   // 512 x 64
#define OFF_R2  229376   // 512 x 512
#define OFF_R3  491520   // 128 x 512

// ======================= edge utilities ====================================
__device__ __forceinline__ void load_edge(const void* ei, int is32, int idx,
                                          int& src, int& dst) {
    if (is32) {
        src = ((const int*)ei)[idx];
        dst = ((const int*)ei)[NEDGES + idx];
    } else {
        src = (int)((const long long*)ei)[idx];
        dst = (int)((const long long*)ei)[NEDGES + idx];
    }
}

__global__ void detect_idx_kernel(const long long* ei, int* flag) {
    int i = blockIdx.x * blockDim.x + threadIdx.x;
    if (i >= NEDGES) return;
    long long v = ei[i];
    if (v < 0 || v >= (long long)NNODES) atomicOr(flag, 1);
}

__global__ void hist_kernel(const void* __restrict__ ei, const int* __restrict__ flag,
                            int* __restrict__ counts) {
    int i = blockIdx.x * blockDim.x + threadIdx.x;
    if (i >= NEDGES) return;
    int s, d;
    load_edge(ei, *flag, i, s, d);
    atomicAdd(&counts[d], 1);
}

// single block, 1024 threads, 100 counts each (1024*100 == NNODES)
__global__ void scan_kernel(int* __restrict__ counts_cursor, int* __restrict__ offs) {
    __shared__ int part[1024];
    int t = threadIdx.x;
    int base = t * 100;
    int sum = 0;
    for (int i = 0; i < 100; i++) sum += counts_cursor[base + i];
    part[t] = sum;
    __syncthreads();
    for (int d = 1; d < 1024; d <<= 1) {
        int v = (t >= d) ? part[t - d] : 0;
        __syncthreads();
        part[t] += v;
        __syncthreads();
    }
    int run = (t == 0) ? 0 : part[t - 1];
    for (int i = 0; i < 100; i++) {
        int c = counts_cursor[base + i];
        offs[base + i] = run;
        counts_cursor[base + i] = run;   // cursor for scatter
        run += c;
    }
    if (t == 1023) offs[NNODES] = run;
}

__global__ void scatter_kernel(const void* __restrict__ ei, const int* __restrict__ flag,
                               int* __restrict__ cursor, int* __restrict__ srcarr) {
    int i = blockIdx.x * blockDim.x + threadIdx.x;
    if (i >= NEDGES) return;
    int s, d;
    load_edge(ei, *flag, i, s, d);
    int pos = atomicAdd(&cursor[d], 1);
    srcarr[pos] = s;
}

// ======================= misc conversions ==================================
__global__ void conv_A_kernel(const float* __restrict__ A,
                              __nv_bfloat16* __restrict__ hi, __nv_bfloat16* __restrict__ lo,
                              int M, int K, int Kpad) {
    int i = blockIdx.x * blockDim.x + threadIdx.x;
    if (i >= M * Kpad) return;
    int m = i / Kpad, k = i - m * Kpad;
    float v = (k < K) ? A[(size_t)m * K + k] : 0.f;
    __nv_bfloat16 h16 = __float2bfloat16(v);
    hi[i] = h16;
    lo[i] = __float2bfloat16(v - __bfloat162float(h16));
}

__global__ void conv_B_kernel(const float* __restrict__ B,
                              __nv_bfloat16* __restrict__ hi, __nv_bfloat16* __restrict__ lo,
                              int K, int N, int Kpad, int Npad) {
    int i = blockIdx.x * blockDim.x + threadIdx.x;
    if (i >= Npad * Kpad) return;
    int n = i / Kpad, k = i - n * Kpad;
    float v = (k < K && n < N) ? B[(size_t)k * N + n] : 0.f;
    __nv_bfloat16 h16 = __float2bfloat16(v);
    hi[i] = h16;
    lo[i] = __float2bfloat16(v - __bfloat162float(h16));
}

// ======================= bf16-split mma.sync GEMM ==========================
// 512 threads = 16 warps (4 warpM x 4 warpN), warp tile 32 x (N8*8).
// CTA tile 128 x NBLK (NBLK = N8*32). K chunks of 64, double buffered.
// N8=8: NBLK=256 (layer GEMMs, fused attn logits). N8=4: NBLK=128 (fc, r3).
template<int N8>
__global__ __launch_bounds__(512, 1)
void gemm_mma(const __nv_bfloat16* __restrict__ Ahi, const __nv_bfloat16* __restrict__ Alo,
              int Kpad,
              const __nv_bfloat16* __restrict__ Bhi, const __nv_bfloat16* __restrict__ Blo,
              float* outf, int nwrite, int ldout,
              __nv_bfloat16* ohi, __nv_bfloat16* olo, int ldo2,
              const float* __restrict__ bias, int act,
              const float* __restrict__ a_src, const float* __restrict__ a_dst,
              float* als, float* ald)
{
    constexpr int NBLK = N8 * 32;
    constexpr uint32_t BSTAGE = (uint32_t)NBLK * 128u;   // bytes per B half
    constexpr uint32_t STAGE = 32768u + 2u * BSTAGE;
    extern __shared__ char sm_raw[];
    uint32_t sb = smem_to_u32(sm_raw);
    int tid = threadIdx.x, wid = tid >> 5, lane = tid & 31;
    int warpM = wid & 3, warpN = wid >> 2;
    int mBase = blockIdx.x * 128;
    int nBase = blockIdx.y * NBLK;
    const int NC = Kpad >> 6;
    const int kp = lane & 3;
    const int lq = lane >> 2;

    float acc[2][N8][4];
#pragma unroll
    for (int i = 0; i < 2; i++)
#pragma unroll
        for (int j = 0; j < N8; j++)
#pragma unroll
            for (int q = 0; q < 4; q++) acc[i][j][q] = 0.f;

    // ---- prologue: stage 0 ----
    {
        uint32_t base = sb;
#pragma unroll
        for (int i = 0; i < 4; i++) {                 // A: 2048 granules
            int u = tid + i * 512;
            int hl = u >> 10, rem = u & 1023, row = rem >> 3, g = rem & 7;
            const __nv_bfloat16* src = (hl ? Alo : Ahi) + (size_t)(mBase + row) * Kpad + g * 8;
            cp16(base + hl * 16384 + row * 128 + (((g ^ (row & 7)) << 4)), src);
        }
#pragma unroll
        for (int i = 0; i < N8; i++) {                // B: NBLK*16 granules
            int u = tid + i * 512;
            int hl = (u >= NBLK * 8);
            int rem = u - hl * NBLK * 8;
            int row = rem >> 3, g = rem & 7;
            const __nv_bfloat16* src = (hl ? Blo : Bhi) + (size_t)(nBase + row) * Kpad + g * 8;
            cp16(base + 32768 + hl * BSTAGE + row * 128 + (((g ^ (row & 7)) << 4)), src);
        }
        asm volatile("cp.async.commit_group;" ::: "memory");
    }

    for (int c = 0; c < NC; c++) {
        if (c + 1 < NC) {
            uint32_t base = sb + ((c + 1) & 1) * STAGE;
            int ko = (c + 1) * 64;
#pragma unroll
            for (int i = 0; i < 4; i++) {
                int u = tid + i * 512;
                int hl = u >> 10, rem = u & 1023, row = rem >> 3, g = rem & 7;
                const __nv_bfloat16* src = (hl ? Alo : Ahi) + (size_t)(mBase + row) * Kpad + ko + g * 8;
                cp16(base + hl * 16384 + row * 128 + (((g ^ (row & 7)) << 4)), src);
            }
#pragma unroll
            for (int i = 0; i < N8; i++) {
                int u = tid + i * 512;
                int hl = (u >= NBLK * 8);
                int rem = u - hl * NBLK * 8;
                int row = rem >> 3, g = rem & 7;
                const __nv_bfloat16* src = (hl ? Blo : Bhi) + (size_t)(nBase + row) * Kpad + ko + g * 8;
                cp16(base + 32768 + hl * BSTAGE + row * 128 + (((g ^ (row & 7)) << 4)), src);
            }
            asm volatile("cp.async.commit_group;" ::: "memory");
            asm volatile("cp.async.wait_group 1;" ::: "memory");
        } else {
            asm volatile("cp.async.wait_group 0;" ::: "memory");
        }
        __syncthreads();

        uint32_t aB = sb + (c & 1) * STAGE;
        uint32_t bB = aB + 32768;
#pragma unroll
        for (int k16 = 0; k16 < 4; k16++) {
            int c0 = k16 * 8;
            uint32_t Ah[2][4], Al[2][4];
#pragma unroll
            for (int mf = 0; mf < 2; mf++) {
                int r0 = warpM * 32 + mf * 16 + lq;
                Ah[mf][0] = lds32(smaddr(aB, r0,     c0 + kp));
                Ah[mf][1] = lds32(smaddr(aB, r0 + 8, c0 + kp));
                Ah[mf][2] = lds32(smaddr(aB, r0,     c0 + kp + 4));
                Ah[mf][3] = lds32(smaddr(aB, r0 + 8, c0 + kp + 4));
                Al[mf][0] = lds32(smaddr(aB + 16384, r0,     c0 + kp));
                Al[mf][1] = lds32(smaddr(aB + 16384, r0 + 8, c0 + kp));
                Al[mf][2] = lds32(smaddr(aB + 16384, r0,     c0 + kp + 4));
                Al[mf][3] = lds32(smaddr(aB + 16384, r0 + 8, c0 + kp + 4));
            }
#pragma unroll
            for (int n8 = 0; n8 < N8; n8++) {
                int n = warpN * N8 * 8 + n8 * 8 + lq;
                uint32_t bh0 = lds32(smaddr(bB, n, c0 + kp));
                uint32_t bh1 = lds32(smaddr(bB, n, c0 + kp + 4));
                uint32_t bl0 = lds32(smaddr(bB + BSTAGE, n, c0 + kp));
                uint32_t bl1 = lds32(smaddr(bB + BSTAGE, n, c0 + kp + 4));
#pragma unroll
                for (int mf = 0; mf < 2; mf++) {
                    mma_bf16(acc[mf][n8], Ah[mf][0], Ah[mf][1], Ah[mf][2], Ah[mf][3], bh0, bh1);
                    mma_bf16(acc[mf][n8], Ah[mf][0], Ah[mf][1], Ah[mf][2], Ah[mf][3], bl0, bl1);
                    mma_bf16(acc[mf][n8], Al[mf][0], Al[mf][1], Al[mf][2], Al[mf][3], bh0, bh1);
                }
            }
        }
        __syncthreads();
    }

    // ---- epilogue ----
    int limit = nwrite - nBase;
    float s1[2][2] = {{0.f, 0.f}, {0.f, 0.f}};
    float s2[2][2] = {{0.f, 0.f}, {0.f, 0.f}};
#pragma unroll
    for (int mf = 0; mf < 2; mf++) {
        int gr0 = mBase + warpM * 32 + mf * 16 + lq;
#pragma unroll
        for (int n8 = 0; n8 < N8; n8++) {
            int cl = warpN * N8 * 8 + n8 * 8 + kp * 2;
            float v[4];
#pragma unroll
            for (int q = 0; q < 4; q++) v[q] = acc[mf][n8][q];
#pragma unroll
            for (int q = 0; q < 4; q++) {
                int col = cl + (q & 1);
                if (col < limit) {
                    float x = v[q];
                    if (bias) x += bias[nBase + col];
                    if (act) x = x > 0.f ? x : 0.01f * x;
                    v[q] = x;
                }
            }
            if (a_src) {
                s1[mf][0] += v[0] * a_src[cl] + v[1] * a_src[cl + 1];
                s2[mf][0] += v[0] * a_dst[cl] + v[1] * a_dst[cl + 1];
                s1[mf][1] += v[2] * a_src[cl] + v[3] * a_src[cl + 1];
                s2[mf][1] += v[2] * a_dst[cl] + v[3] * a_dst[cl + 1];
            }
            if (outf) {
                if (cl + 1 < limit) {
                    *(float2*)(outf + (size_t)gr0 * ldout + nBase + cl) = make_float2(v[0], v[1]);
                    *(float2*)(outf + (size_t)(gr0 + 8) * ldout + nBase + cl) = make_float2(v[2], v[3]);
                } else if (cl < limit) {
                    outf[(size_t)gr0 * ldout + nBase + cl] = v[0];
                    outf[(size_t)(gr0 + 8) * ldout + nBase + cl] = v[2];
                }
            }
            if (ohi && cl < limit) {
                __nv_bfloat16 h0 = __float2bfloat16(v[0]);
                __nv_bfloat16 h1 = __float2bfloat16(v[1]);
                __nv_bfloat16 l0 = __float2bfloat16(v[0] - __bfloat162float(h0));
                __nv_bfloat16 l1 = __float2bfloat16(v[1] - __bfloat162float(h1));
                *(__nv_bfloat162*)(ohi + (size_t)gr0 * ldo2 + nBase + cl) = __nv_bfloat162(h0, h1);
                *(__nv_bfloat162*)(olo + (size_t)gr0 * ldo2 + nBase + cl) = __nv_bfloat162(l0, l1);
                __nv_bfloat16 h2 = __float2bfloat16(v[2]);
                __nv_bfloat16 h3 = __float2bfloat16(v[3]);
                __nv_bfloat16 l2 = __float2bfloat16(v[2] - __bfloat162float(h2));
                __nv_bfloat16 l3 = __float2bfloat16(v[3] - __bfloat162float(h3));
                *(__nv_bfloat162*)(ohi + (size_t)(gr0 + 8) * ldo2 + nBase + cl) = __nv_bfloat162(h2, h3);
                *(__nv_bfloat162*)(olo + (size_t)(gr0 + 8) * ldo2 + nBase + cl) = __nv_bfloat162(l2, l3);
            }
        }
    }
    if (a_src) {
        // warpN == head (N8 == 8: warp covers 64 cols == one head)
#pragma unroll
        for (int mf = 0; mf < 2; mf++)
#pragma unroll
            for (int hf = 0; hf < 2; hf++) {
                s1[mf][hf] += __shfl_xor_sync(0xFFFFFFFF, s1[mf][hf], 1);
                s1[mf][hf] += __shfl_xor_sync(0xFFFFFFFF, s1[mf][hf], 2);
                s2[mf][hf] += __shfl_xor_sync(0xFFFFFFFF, s2[mf][hf], 1);
                s2[mf][hf] += __shfl_xor_sync(0xFFFFFFFF, s2[mf][hf], 2);
            }
        if ((lane & 3) == 0) {
#pragma unroll
            for (int mf = 0; mf < 2; mf++)
#pragma unroll
                for (int hf = 0; hf < 2; hf++) {
                    int gr = mBase + warpM * 32 + mf * 16 + hf * 8 + lq;
                    als[gr * 4 + warpN] = s1[mf][hf];
                    ald[gr * 4 + warpN] = s2[mf][hf];
                }
        }
    }
}

// ======================= fused GAT aggregation (one warp per dst) ==========
__global__ __launch_bounds__(256)
void gat_agg(const int* __restrict__ offs, const int* __restrict__ srcarr,
             const float4* __restrict__ als4, const float4* __restrict__ ald4,
             const float* __restrict__ h,
             const float* __restrict__ bias, int act,
             __nv_bfloat16* __restrict__ ohi, __nv_bfloat16* __restrict__ olo)
{
    int w = (blockIdx.x * blockDim.x + threadIdx.x) >> 5;
    int lane = threadIdx.x & 31;
    if (w >= NNODES) return;
    int n = w;
    int beg = offs[n], end = offs[n + 1];
    float4 aldn = ald4[n];
    float4 an = als4[n];
    float4 eself = leaky4_02(make_float4(an.x + aldn.x, an.y + aldn.y,
                                         an.z + aldn.z, an.w + aldn.w));
    // ---- pass 1: segment max ----
    float4 m = eself;
    for (int j = beg + lane; j < end; j += 32) {
        int s = srcarr[j];
        float4 a = als4[s];
        float4 e = leaky4_02(make_float4(a.x + aldn.x, a.y + aldn.y,
                                         a.z + aldn.z, a.w + aldn.w));
        m.x = fmaxf(m.x, e.x); m.y = fmaxf(m.y, e.y);
        m.z = fmaxf(m.z, e.z); m.w = fmaxf(m.w, e.w);
    }
#pragma unroll
    for (int o = 16; o; o >>= 1) {
        m.x = fmaxf(m.x, __shfl_xor_sync(0xFFFFFFFF, m.x, o));
        m.y = fmaxf(m.y, __shfl_xor_sync(0xFFFFFFFF, m.y, o));
        m.z = fmaxf(m.z, __shfl_xor_sync(0xFFFFFFFF, m.z, o));
        m.w = fmaxf(m.w, __shfl_xor_sync(0xFFFFFFFF, m.w, o));
    }
    // ---- pass 2: p, sum, gather-accumulate ----
    float acc[8] = {0.f, 0.f, 0.f, 0.f, 0.f, 0.f, 0.f, 0.f};
    float4 psum = make_float4(0.f, 0.f, 0.f, 0.f);
    for (int base = beg; base < end; base += 32) {
        int j = base + lane;
        int valid = j < end;
        int s = valid ? srcarr[j] : 0;
        float4 p = make_float4(0.f, 0.f, 0.f, 0.f);
        if (valid) {
            float4 a = als4[s];
            float4 e = leaky4_02(make_float4(a.x + aldn.x, a.y + aldn.y,
                                             a.z + aldn.z, a.w + aldn.w));
            p.x = __expf(e.x - m.x); p.y = __expf(e.y - m.y);
            p.z = __expf(e.z - m.z); p.w = __expf(e.w - m.w);
            psum.x += p.x; psum.y += p.y; psum.z += p.z; psum.w += p.w;
        }
        int cnt = end - base; if (cnt > 32) cnt = 32;
        for (int jj = 0; jj < cnt; jj++) {
            int   sj = __shfl_sync(0xFFFFFFFF, s, jj);
            float px = __shfl_sync(0xFFFFFFFF, p.x, jj);
            float py = __shfl_sync(0xFFFFFFFF, p.y, jj);
            float pz = __shfl_sync(0xFFFFFFFF, p.z, jj);
            float pw = __shfl_sync(0xFFFFFFFF, p.w, jj);
            const float4* hf = (const float4*)(h + (size_t)sj * HC);
            float pA = (lane < 16) ? px : py;
            float pB = (lane < 16) ? pz : pw;
            float4 vA = __ldg(&hf[lane]);
            float4 vB = __ldg(&hf[lane + 32]);
            acc[0] += pA * vA.x; acc[1] += pA * vA.y;
            acc[2] += pA * vA.z; acc[3] += pA * vA.w;
            acc[4] += pB * vB.x; acc[5] += pB * vB.y;
            acc[6] += pB * vB.z; acc[7] += pB * vB.w;
        }
    }
#pragma unroll
    for (int o = 16; o; o >>= 1) {
        psum.x += __shfl_xor_sync(0xFFFFFFFF, psum.x, o);
        psum.y += __shfl_xor_sync(0xFFFFFFFF, psum.y, o);
        psum.z += __shfl_xor_sync(0xFFFFFFFF, psum.z, o);
        psum.w += __shfl_xor_sync(0xFFFFFFFF, psum.w, o);
    }
    // self loop contribution
    float4 ps;
    ps.x = __expf(eself.x - m.x); ps.y = __expf(eself.y - m.y);
    ps.z = __expf(eself.z - m.z); ps.w = __expf(eself.w - m.w);
    psum.x += ps.x; psum.y += ps.y; psum.z += ps.z; psum.w += ps.w;
    {
        const float4* hf = (const float4*)(h + (size_t)n * HC);
        float pA = (lane < 16) ? ps.x : ps.y;
        float pB = (lane < 16) ? ps.z : ps.w;
        float4 vA = hf[lane];
        float4 vB = hf[lane + 32];
        acc[0] += pA * vA.x; acc[1] += pA * vA.y;
        acc[2] += pA * vA.z; acc[3] += pA * vA.w;
        acc[4] += pB * vB.x; acc[5] += pB * vB.y;
        acc[6] += pB * vB.z; acc[7] += pB * vB.w;
    }
    // ---- epilogue: divide, bias, act, write bf16 hi/lo ----
    float sA = (lane < 16) ? psum.x : psum.y;
    float sB = (lane < 16) ? psum.z : psum.w;
    const float4* b4 = (const float4*)bias;
    float4 bA = b4[lane], bB = b4[lane + 32];
    float v[8];
    float rA = 1.f / sA, rB = 1.f / sB;
    v[0] = acc[0] * rA + bA.x; v[1] = acc[1] * rA + bA.y;
    v[2] = acc[2] * rA + bA.z; v[3] = acc[3] * rA + bA.w;
    v[4] = acc[4] * rB + bB.x; v[5] = acc[5] * rB + bB.y;
    v[6] = acc[6] * rB + bB.z; v[7] = acc[7] * rB + bB.w;
    if (act) {
#pragma unroll
        for (int q = 0; q < 8; q++) v[q] = v[q] > 0.f ? v[q] : 0.01f * v[q];
    }
    size_t i0 = (size_t)n * HC + lane * 4;
    size_t i1 = (size_t)n * HC + (lane + 32) * 4;
#pragma unroll
    for (int g = 0; g < 2; g++) {
        size_t ix = g ? i1 : i0;
        const float* vv = v + g * 4;
        __nv_bfloat16 h0 = __float2bfloat16(vv[0]);
        __nv_bfloat16 h1 = __float2bfloat16(vv[1]);
        __nv_bfloat16 h2 = __float2bfloat16(vv[2]);
        __nv_bfloat16 h3 = __float2bfloat16(vv[3]);
        *(__nv_bfloat162*)(ohi + ix)     = __nv_bfloat162(h0, h1);
        *(__nv_bfloat162*)(ohi + ix + 2) = __nv_bfloat162(h2, h3);
        __nv_bfloat16 l0 = __float2bfloat16(vv[0] - __bfloat162float(h0));
        __nv_bfloat16 l1 = __float2bfloat16(vv[1] - __bfloat162float(h1));
        __nv_bfloat16 l2 = __float2bfloat16(vv[2] - __bfloat162float(h2));
        __nv_bfloat16 l3 = __float2bfloat16(vv[3] - __bfloat162float(h3));
        *(__nv_bfloat162*)(olo + ix)     = __nv_bfloat162(l0, l1);
        *(__nv_bfloat162*)(olo + ix + 2) = __nv_bfloat162(l2, l3);
    }
}

// ======================= host orchestration ================================
#define SMEM_N8  (2 * (32768 + 2 * 256 * 128))   // 196608
#define SMEM_N4  (2 * (32768 + 2 * 128 * 128))   // 131072

extern "C" void kernel_launch(void* const* d_in, const int* in_sizes, int n_in,
                              void* d_out, int out_size)
{
    const float* x    = (const float*)d_in[0];
    const void*  ei   = d_in[1];
    const float* root = (const float*)d_in[2];
    const float* W[3]  = {(const float*)d_in[3], (const float*)d_in[7],  (const float*)d_in[11]};
    const float* aS[3] = {(const float*)d_in[4], (const float*)d_in[8],  (const float*)d_in[12]};
    const float* aD[3] = {(const float*)d_in[5], (const float*)d_in[9],  (const float*)d_in[13]};
    const float* bb[3] = {(const float*)d_in[6], (const float*)d_in[10], (const float*)d_in[14]};
    const float* fc_w = (const float*)d_in[15];
    const float* fc_b = (const float*)d_in[16];
    const float* r_w1 = (const float*)d_in[17];
    const float* r_b1 = (const float*)d_in[18];
    const float* r_w2 = (const float*)d_in[19];
    const float* r_b2 = (const float*)d_in[20];
    const float* r_w3 = (const float*)d_in[21];
    const float* r_b3 = (const float*)d_in[22];

    float *p_h, *p_als, *p_ald;
    int *p_off, *p_cur, *p_srcarr, *p_flag;
    __nv_bfloat16 *p_Ahi, *p_Alo, *p_Bhi, *p_Blo, *p_rAh, *p_rAl, *p_r1h, *p_r1l, *p_r2h, *p_r2l;
    cudaGetSymbolAddress((void**)&p_h,   g_h);
    cudaGetSymbolAddress((void**)&p_als, g_als);
    cudaGetSymbolAddress((void**)&p_ald, g_ald);
    cudaGetSymbolAddress((void**)&p_off, g_off);
    cudaGetSymbolAddress((void**)&p_cur, g_cur);
    cudaGetSymbolAddress((void**)&p_srcarr, g_srcarr);
    cudaGetSymbolAddress((void**)&p_flag, g_is32);
    cudaGetSymbolAddress((void**)&p_Ahi, g_Ahi);
    cudaGetSymbolAddress((void**)&p_Alo, g_Alo);
    cudaGetSymbolAddress((void**)&p_Bhi, g_Bhi);
    cudaGetSymbolAddress((void**)&p_Blo, g_Blo);
    cudaGetSymbolAddress((void**)&p_rAh, g_rAh);
    cudaGetSymbolAddress((void**)&p_rAl, g_rAl);
    cudaGetSymbolAddress((void**)&p_r1h, g_r1h);
    cudaGetSymbolAddress((void**)&p_r1l, g_r1l);
    cudaGetSymbolAddress((void**)&p_r2h, g_r2h);
    cudaGetSymbolAddress((void**)&p_r2l, g_r2l);

    static int smem_set = 0;
    if (!smem_set) {
        cudaFuncSetAttribute(gemm_mma<8>, cudaFuncAttributeMaxDynamicSharedMemorySize, SMEM_N8);
        cudaFuncSetAttribute(gemm_mma<4>, cudaFuncAttributeMaxDynamicSharedMemorySize, SMEM_N4);
        smem_set = 1;
    }

    // ---- CSR build (once per call, reused by all 3 layers) ----
    cudaMemsetAsync(p_flag, 0, sizeof(int));
    detect_idx_kernel<<<(NEDGES + 255) / 256, 256>>>((const long long*)ei, p_flag);
    cudaMemsetAsync(p_cur, 0, NNODES * sizeof(int));
    hist_kernel<<<(NEDGES + 255) / 256, 256>>>(ei, p_flag, p_cur);
    scan_kernel<<<1, 1024>>>(p_cur, p_off);
    scatter_kernel<<<(NEDGES + 255) / 256, 256>>>(ei, p_flag, p_cur, p_srcarr);

    // ---- weight conversions ----
    conv_B_kernel<<<(256 * 128 + 255) / 256, 256>>>(W[0], p_Bhi + OFF_W0, p_Blo + OFF_W0, 80, 256, 128, 256);
    conv_B_kernel<<<(256 * 256 + 255) / 256, 256>>>(W[1], p_Bhi + OFF_W1, p_Blo + OFF_W1, 256, 256, 256, 256);
    conv_B_kernel<<<(256 * 256 + 255) / 256, 256>>>(W[2], p_Bhi + OFF_W2, p_Blo + OFF_W2, 256, 256, 256, 256);
    conv_B_kernel<<<(128 * 256 + 255) / 256, 256>>>(fc_w, p_Bhi + OFF_FC, p_Blo + OFF_FC, 256, 80, 256, 128);
    conv_B_kernel<<<(512 * 64 + 255) / 256, 256>>>(r_w1, p_Bhi + OFF_R1, p_Blo + OFF_R1, 60, 512, 64, 512);
    conv_B_kernel<<<(512 * 512 + 255) / 256, 256>>>(r_w2, p_Bhi + OFF_R2, p_Blo + OFF_R2, 512, 512, 512, 512);
    conv_B_kernel<<<(128 * 512 + 255) / 256, 256>>>(r_w3, p_Bhi + OFF_R3, p_Blo + OFF_R3, 512, 60, 512, 128);

    // x -> bf16 hi/lo, K padded 80->128
    conv_A_kernel<<<(NNODES * 128 + 255) / 256, 256>>>(x, p_Ahi, p_Alo, NNODES, 80, 128);

    const int Kpad[3] = {128, 256, 256};
    const __nv_bfloat16* Boff_hi[3] = {p_Bhi + OFF_W0, p_Bhi + OFF_W1, p_Bhi + OFF_W2};
    const __nv_bfloat16* Boff_lo[3] = {p_Blo + OFF_W0, p_Blo + OFF_W1, p_Blo + OFF_W2};

    for (int L = 0; L < 3; L++) {
        gemm_mma<8><<<dim3(NNODES / 128, 1), 512, SMEM_N8>>>(
            p_Ahi, p_Alo, Kpad[L], Boff_hi[L], Boff_lo[L],
            p_h, 256, 256, nullptr, nullptr, 0,
            nullptr, 0, aS[L], aD[L], p_als, p_ald);
        int act = (L < 2) ? 1 : 0;
        gat_agg<<<NNODES / 8, 256>>>(p_off, p_srcarr,
                                     (const float4*)p_als, (const float4*)p_ald,
                                     p_h, bb[L], act, p_Ahi, p_Alo);
    }

    // rot = h @ fc_w + fc_b -> d_out[0 : N*80]  (NBLK=128, only 80 valid)
    float* rot = (float*)d_out;
    gemm_mma<4><<<dim3(NNODES / 128, 1), 512, SMEM_N4>>>(
        p_Ahi, p_Alo, 256, p_Bhi + OFF_FC, p_Blo + OFF_FC,
        rot, 80, 80, nullptr, nullptr, 0,
        fc_b, 0, nullptr, nullptr, nullptr, nullptr);

    // root MLP
    conv_A_kernel<<<(4096 * 64 + 255) / 256, 256>>>(root, p_rAh, p_rAl, 4096, 60, 64);
    gemm_mma<8><<<dim3(32, 2), 512, SMEM_N8>>>(
        p_rAh, p_rAl, 64, p_Bhi + OFF_R1, p_Blo + OFF_R1,
        nullptr, 512, 0, p_r1h, p_r1l, 512,
        r_b1, 1, nullptr, nullptr, nullptr, nullptr);
    gemm_mma<8><<<dim3(32, 2), 512, SMEM_N8>>>(
        p_r1h, p_r1l, 512, p_Bhi + OFF_R2, p_Blo + OFF_R2,
        nullptr, 512, 0, p_r2h, p_r2l, 512,
        r_b2, 1, nullptr, nullptr, nullptr, nullptr);
    float* root_out = rot + (size_t)NNODES * 80;
    gemm_mma<4><<<dim3(32, 1), 512, SMEM_N4>>>(
        p_r2h, p_r2l, 512, p_Bhi + OFF_R3, p_Blo + OFF_R3,
        root_out, 60, 60, nullptr, nullptr, 0,
        r_b3, 0, nullptr, nullptr, nullptr, nullptr);
}

// round 8
// speedup vs baseline: 1.1602x; 1.0766x over previous
#include <cuda_runtime.h>
#include <cuda_bf16.h>
#include <cuda_fp16.h>
#include <cstdint>
#include <math.h>

// Problem constants (fixed by the dataset)
#define NNODES 102400
#define NEDGES 409600
#define HC 256
#define NH 4

// ======================= small helpers =====================================
__device__ __forceinline__ uint32_t smem_to_u32(const void* p) {
    uint32_t a;
    asm("{ .reg .u64 t; cvta.to.shared.u64 t, %1; cvt.u32.u64 %0, t; }" : "=r"(a) : "l"(p));
    return a;
}
__device__ __forceinline__ void cp16(uint32_t s, const void* g) {
    asm volatile("cp.async.cg.shared.global [%0], [%1], 16;" :: "r"(s), "l"(g));
}
__device__ __forceinline__ uint32_t lds32(uint32_t a) {
    uint32_t v; asm volatile("ld.shared.b32 %0, [%1];" : "=r"(v) : "r"(a)); return v;
}
__device__ __forceinline__ uint32_t smaddr(uint32_t base, int r, int c) {
    return base + r * 128 + ((((c >> 2) ^ (r & 7)) << 4)) + ((c & 3) << 2);
}
__device__ __forceinline__ void mma_bf16(float* d, uint32_t a0, uint32_t a1, uint32_t a2,
                                         uint32_t a3, uint32_t b0, uint32_t b1) {
    asm volatile(
        "mma.sync.aligned.m16n8k16.row.col.f32.bf16.bf16.f32 "
        "{%0,%1,%2,%3}, {%4,%5,%6,%7}, {%8,%9}, {%0,%1,%2,%3};"
        : "+f"(d[0]), "+f"(d[1]), "+f"(d[2]), "+f"(d[3])
        : "r"(a0), "r"(a1), "r"(a2), "r"(a3), "r"(b0), "r"(b1));
}
__device__ __forceinline__ float4 leaky4_02(float4 v) {
    v.x = v.x > 0.f ? v.x : 0.2f * v.x;
    v.y = v.y > 0.f ? v.y : 0.2f * v.y;
    v.z = v.z > 0.f ? v.z : 0.2f * v.z;
    v.w = v.w > 0.f ? v.w : 0.2f * v.w;
    return v;
}

// ======================= scratch (device globals) ==========================
__device__ __align__(16) __half g_h[(size_t)NNODES * HC];   // fp16 transformed feats
__device__ __align__(16) float g_als[NNODES * NH];
__device__ __align__(16) float g_ald[NNODES * NH];
__device__ int g_off[NNODES + 1];
__device__ int g_cur[NNODES];
__device__ int g_srcarr[NEDGES];
__device__ int g_is32;
// bf16-split operands
__device__ __align__(16) __nv_bfloat16 g_Ahi[(size_t)NNODES * HC];
__device__ __align__(16) __nv_bfloat16 g_Alo[(size_t)NNODES * HC];
__device__ __align__(16) __nv_bfloat16 g_Bhi[600000];
__device__ __align__(16) __nv_bfloat16 g_Blo[600000];
__device__ __align__(16) __nv_bfloat16 g_rAh[4096 * 64];
__device__ __align__(16) __nv_bfloat16 g_rAl[4096 * 64];
__device__ __align__(16) __nv_bfloat16 g_r1h[4096 * 512];
__device__ __align__(16) __nv_bfloat16 g_r1l[4096 * 512];
__device__ __align__(16) __nv_bfloat16 g_r2h[4096 * 512];
__device__ __align__(16) __nv_bfloat16 g_r2l[4096 * 512];

// B buffer element offsets (B stored [Npad][Kpad], hi/lo, zero padded)
#define OFF_W0  0        // 256 x 128
#define OFF_W1  32768    // 256 x 256
#define OFF_W2  98304    // 256 x 256
#define OFF_FC  163840   // 128 x 256
#define OFF_R1  196608   // 512 x 64
#define OFF_R2  229376   // 512 x 512
#define OFF_R3  491520   // 128 x 512

// ======================= edge utilities ====================================
__device__ __forceinline__ void load_edge(const void* ei, int is32, int idx,
                                          int& src, int& dst) {
    if (is32) {
        src = ((const int*)ei)[idx];
        dst = ((const int*)ei)[NEDGES + idx];
    } else {
        src = (int)((const long long*)ei)[idx];
        dst = (int)((const long long*)ei)[NEDGES + idx];
    }
}

__global__ void detect_idx_kernel(const long long* ei, int* flag) {
    int i = blockIdx.x * blockDim.x + threadIdx.x;
    if (i >= NEDGES) return;
    long long v = ei[i];
    if (v < 0 || v >= (long long)NNODES) atomicOr(flag, 1);
}

__global__ void hist_kernel(const void* __restrict__ ei, const int* __restrict__ flag,
                            int* __restrict__ counts) {
    int i = blockIdx.x * blockDim.x + threadIdx.x;
    if (i >= NEDGES) return;
    int s, d;
    load_edge(ei, *flag, i, s, d);
    atomicAdd(&counts[d], 1);
}

// single block, 1024 threads, 100 counts each (1024*100 == NNODES)
__global__ void scan_kernel(int* __restrict__ counts_cursor, int* __restrict__ offs) {
    __shared__ int part[1024];
    int t = threadIdx.x;
    int base = t * 100;
    int sum = 0;
    for (int i = 0; i < 100; i++) sum += counts_cursor[base + i];
    part[t] = sum;
    __syncthreads();
    for (int d = 1; d < 1024; d <<= 1) {
        int v = (t >= d) ? part[t - d] : 0;
        __syncthreads();
        part[t] += v;
        __syncthreads();
    }
    int run = (t == 0) ? 0 : part[t - 1];
    for (int i = 0; i < 100; i++) {
        int c = counts_cursor[base + i];
        offs[base + i] = run;
        counts_cursor[base + i] = run;   // cursor for scatter
        run += c;
    }
    if (t == 1023) offs[NNODES] = run;
}

__global__ void scatter_kernel(const void* __restrict__ ei, const int* __restrict__ flag,
                               int* __restrict__ cursor, int* __restrict__ srcarr) {
    int i = blockIdx.x * blockDim.x + threadIdx.x;
    if (i >= NEDGES) return;
    int s, d;
    load_edge(ei, *flag, i, s, d);
    int pos = atomicAdd(&cursor[d], 1);
    srcarr[pos] = s;
}

// ======================= misc conversions ==================================
__global__ void conv_A_kernel(const float* __restrict__ A,
                              __nv_bfloat16* __restrict__ hi, __nv_bfloat16* __restrict__ lo,
                              int M, int K, int Kpad) {
    int i = blockIdx.x * blockDim.x + threadIdx.x;
    if (i >= M * Kpad) return;
    int m = i / Kpad, k = i - m * Kpad;
    float v = (k < K) ? A[(size_t)m * K + k] : 0.f;
    __nv_bfloat16 h16 = __float2bfloat16(v);
    hi[i] = h16;
    lo[i] = __float2bfloat16(v - __bfloat162float(h16));
}

__global__ void conv_B_kernel(const float* __restrict__ B,
                              __nv_bfloat16* __restrict__ hi, __nv_bfloat16* __restrict__ lo,
                              int K, int N, int Kpad, int Npad) {
    int i = blockIdx.x * blockDim.x + threadIdx.x;
    if (i >= Npad * Kpad) return;
    int n = i / Kpad, k = i - n * Kpad;
    float v = (k < K && n < N) ? B[(size_t)k * N + n] : 0.f;
    __nv_bfloat16 h16 = __float2bfloat16(v);
    hi[i] = h16;
    lo[i] = __float2bfloat16(v - __bfloat162float(h16));
}

// ======================= bf16-split mma.sync GEMM ==========================
// 512 threads = 16 warps (4 warpM x 4 warpN), warp tile 32 x (N8*8).
// CTA tile 128 x NBLK (NBLK = N8*32). K chunks of 64, double buffered.
// N8=8: NBLK=256 (layer GEMMs, fused attn logits). N8=4: NBLK=128 (fc, r3).
template<int N8>
__global__ __launch_bounds__(512, 1)
void gemm_mma(const __nv_bfloat16* __restrict__ Ahi, const __nv_bfloat16* __restrict__ Alo,
              int Kpad,
              const __nv_bfloat16* __restrict__ Bhi, const __nv_bfloat16* __restrict__ Blo,
              float* outf, __half* outh, int nwrite, int ldout,
              __nv_bfloat16* ohi, __nv_bfloat16* olo, int ldo2,
              const float* __restrict__ bias, int act,
              const float* __restrict__ a_src, const float* __restrict__ a_dst,
              float* als, float* ald)
{
    constexpr int NBLK = N8 * 32;
    constexpr uint32_t BSTAGE = (uint32_t)NBLK * 128u;   // bytes per B half
    constexpr uint32_t STAGE = 32768u + 2u * BSTAGE;
    extern __shared__ char sm_raw[];
    uint32_t sb = smem_to_u32(sm_raw);
    int tid = threadIdx.x, wid = tid >> 5, lane = tid & 31;
    int warpM = wid & 3, warpN = wid >> 2;
    int mBase = blockIdx.x * 128;
    int nBase = blockIdx.y * NBLK;
    const int NC = Kpad >> 6;
    const int kp = lane & 3;
    const int lq = lane >> 2;

    float acc[2][N8][4];
#pragma unroll
    for (int i = 0; i < 2; i++)
#pragma unroll
        for (int j = 0; j < N8; j++)
#pragma unroll
            for (int q = 0; q < 4; q++) acc[i][j][q] = 0.f;

    // ---- prologue: stage 0 ----
    {
        uint32_t base = sb;
#pragma unroll
        for (int i = 0; i < 4; i++) {                 // A: 2048 granules
            int u = tid + i * 512;
            int hl = u >> 10, rem = u & 1023, row = rem >> 3, g = rem & 7;
            const __nv_bfloat16* src = (hl ? Alo : Ahi) + (size_t)(mBase + row) * Kpad + g * 8;
            cp16(base + hl * 16384 + row * 128 + (((g ^ (row & 7)) << 4)), src);
        }
#pragma unroll
        for (int i = 0; i < N8; i++) {                // B: NBLK*16 granules
            int u = tid + i * 512;
            int hl = (u >= NBLK * 8);
            int rem = u - hl * NBLK * 8;
            int row = rem >> 3, g = rem & 7;
            const __nv_bfloat16* src = (hl ? Blo : Bhi) + (size_t)(nBase + row) * Kpad + g * 8;
            cp16(base + 32768 + hl * BSTAGE + row * 128 + (((g ^ (row & 7)) << 4)), src);
        }
        asm volatile("cp.async.commit_group;" ::: "memory");
    }

    for (int c = 0; c < NC; c++) {
        if (c + 1 < NC) {
            uint32_t base = sb + ((c + 1) & 1) * STAGE;
            int ko = (c + 1) * 64;
#pragma unroll
            for (int i = 0; i < 4; i++) {
                int u = tid + i * 512;
                int hl = u >> 10, rem = u & 1023, row = rem >> 3, g = rem & 7;
                const __nv_bfloat16* src = (hl ? Alo : Ahi) + (size_t)(mBase + row) * Kpad + ko + g * 8;
                cp16(base + hl * 16384 + row * 128 + (((g ^ (row & 7)) << 4)), src);
            }
#pragma unroll
            for (int i = 0; i < N8; i++) {
                int u = tid + i * 512;
                int hl = (u >= NBLK * 8);
                int rem = u - hl * NBLK * 8;
                int row = rem >> 3, g = rem & 7;
                const __nv_bfloat16* src = (hl ? Blo : Bhi) + (size_t)(nBase + row) * Kpad + ko + g * 8;
                cp16(base + 32768 + hl * BSTAGE + row * 128 + (((g ^ (row & 7)) << 4)), src);
            }
            asm volatile("cp.async.commit_group;" ::: "memory");
            asm volatile("cp.async.wait_group 1;" ::: "memory");
        } else {
            asm volatile("cp.async.wait_group 0;" ::: "memory");
        }
        __syncthreads();

        uint32_t aB = sb + (c & 1) * STAGE;
        uint32_t bB = aB + 32768;
#pragma unroll
        for (int k16 = 0; k16 < 4; k16++) {
            int c0 = k16 * 8;
            uint32_t Ah[2][4], Al[2][4];
#pragma unroll
            for (int mf = 0; mf < 2; mf++) {
                int r0 = warpM * 32 + mf * 16 + lq;
                Ah[mf][0] = lds32(smaddr(aB, r0,     c0 + kp));
                Ah[mf][1] = lds32(smaddr(aB, r0 + 8, c0 + kp));
                Ah[mf][2] = lds32(smaddr(aB, r0,     c0 + kp + 4));
                Ah[mf][3] = lds32(smaddr(aB, r0 + 8, c0 + kp + 4));
                Al[mf][0] = lds32(smaddr(aB + 16384, r0,     c0 + kp));
                Al[mf][1] = lds32(smaddr(aB + 16384, r0 + 8, c0 + kp));
                Al[mf][2] = lds32(smaddr(aB + 16384, r0,     c0 + kp + 4));
                Al[mf][3] = lds32(smaddr(aB + 16384, r0 + 8, c0 + kp + 4));
            }
#pragma unroll
            for (int n8 = 0; n8 < N8; n8++) {
                int n = warpN * N8 * 8 + n8 * 8 + lq;
                uint32_t bh0 = lds32(smaddr(bB, n, c0 + kp));
                uint32_t bh1 = lds32(smaddr(bB, n, c0 + kp + 4));
                uint32_t bl0 = lds32(smaddr(bB + BSTAGE, n, c0 + kp));
                uint32_t bl1 = lds32(smaddr(bB + BSTAGE, n, c0 + kp + 4));
#pragma unroll
                for (int mf = 0; mf < 2; mf++) {
                    mma_bf16(acc[mf][n8], Ah[mf][0], Ah[mf][1], Ah[mf][2], Ah[mf][3], bh0, bh1);
                    mma_bf16(acc[mf][n8], Ah[mf][0], Ah[mf][1], Ah[mf][2], Ah[mf][3], bl0, bl1);
                    mma_bf16(acc[mf][n8], Al[mf][0], Al[mf][1], Al[mf][2], Al[mf][3], bh0, bh1);
                }
            }
        }
        __syncthreads();
    }

    // ---- epilogue ----
    int limit = nwrite - nBase;
    float s1[2][2] = {{0.f, 0.f}, {0.f, 0.f}};
    float s2[2][2] = {{0.f, 0.f}, {0.f, 0.f}};
#pragma unroll
    for (int mf = 0; mf < 2; mf++) {
        int gr0 = mBase + warpM * 32 + mf * 16 + lq;
#pragma unroll
        for (int n8 = 0; n8 < N8; n8++) {
            int cl = warpN * N8 * 8 + n8 * 8 + kp * 2;
            float v[4];
#pragma unroll
            for (int q = 0; q < 4; q++) v[q] = acc[mf][n8][q];
#pragma unroll
            for (int q = 0; q < 4; q++) {
                int col = cl + (q & 1);
                if (col < limit) {
                    float x = v[q];
                    if (bias) x += bias[nBase + col];
                    if (act) x = x > 0.f ? x : 0.01f * x;
                    v[q] = x;
                }
            }
            if (a_src) {
                s1[mf][0] += v[0] * a_src[cl] + v[1] * a_src[cl + 1];
                s2[mf][0] += v[0] * a_dst[cl] + v[1] * a_dst[cl + 1];
                s1[mf][1] += v[2] * a_src[cl] + v[3] * a_src[cl + 1];
                s2[mf][1] += v[2] * a_dst[cl] + v[3] * a_dst[cl + 1];
            }
            if (outf) {
                if (cl + 1 < limit) {
                    *(float2*)(outf + (size_t)gr0 * ldout + nBase + cl) = make_float2(v[0], v[1]);
                    *(float2*)(outf + (size_t)(gr0 + 8) * ldout + nBase + cl) = make_float2(v[2], v[3]);
                } else if (cl < limit) {
                    outf[(size_t)gr0 * ldout + nBase + cl] = v[0];
                    outf[(size_t)(gr0 + 8) * ldout + nBase + cl] = v[2];
                }
            }
            if (outh && cl < limit) {
                *(__half2*)(outh + (size_t)gr0 * ldout + nBase + cl) = __floats2half2_rn(v[0], v[1]);
                *(__half2*)(outh + (size_t)(gr0 + 8) * ldout + nBase + cl) = __floats2half2_rn(v[2], v[3]);
            }
            if (ohi && cl < limit) {
                __nv_bfloat16 h0 = __float2bfloat16(v[0]);
                __nv_bfloat16 h1 = __float2bfloat16(v[1]);
                __nv_bfloat16 l0 = __float2bfloat16(v[0] - __bfloat162float(h0));
                __nv_bfloat16 l1 = __float2bfloat16(v[1] - __bfloat162float(h1));
                *(__nv_bfloat162*)(ohi + (size_t)gr0 * ldo2 + nBase + cl) = __nv_bfloat162(h0, h1);
                *(__nv_bfloat162*)(olo + (size_t)gr0 * ldo2 + nBase + cl) = __nv_bfloat162(l0, l1);
                __nv_bfloat16 h2 = __float2bfloat16(v[2]);
                __nv_bfloat16 h3 = __float2bfloat16(v[3]);
                __nv_bfloat16 l2 = __float2bfloat16(v[2] - __bfloat162float(h2));
                __nv_bfloat16 l3 = __float2bfloat16(v[3] - __bfloat162float(h3));
                *(__nv_bfloat162*)(ohi + (size_t)(gr0 + 8) * ldo2 + nBase + cl) = __nv_bfloat162(h2, h3);
                *(__nv_bfloat162*)(olo + (size_t)(gr0 + 8) * ldo2 + nBase + cl) = __nv_bfloat162(l2, l3);
            }
        }
    }
    if (a_src) {
        // warpN == head (N8 == 8: warp covers 64 cols == one head)
#pragma unroll
        for (int mf = 0; mf < 2; mf++)
#pragma unroll
            for (int hf = 0; hf < 2; hf++) {
                s1[mf][hf] += __shfl_xor_sync(0xFFFFFFFF, s1[mf][hf], 1);
                s1[mf][hf] += __shfl_xor_sync(0xFFFFFFFF, s1[mf][hf], 2);
                s2[mf][hf] += __shfl_xor_sync(0xFFFFFFFF, s2[mf][hf], 1);
                s2[mf][hf] += __shfl_xor_sync(0xFFFFFFFF, s2[mf][hf], 2);
            }
        if ((lane & 3) == 0) {
#pragma unroll
            for (int mf = 0; mf < 2; mf++)
#pragma unroll
                for (int hf = 0; hf < 2; hf++) {
                    int gr = mBase + warpM * 32 + mf * 16 + hf * 8 + lq;
                    als[gr * 4 + warpN] = s1[mf][hf];
                    ald[gr * 4 + warpN] = s2[mf][hf];
                }
        }
    }
}

// ======================= fused GAT aggregation (one warp per dst) ==========
// h is fp16 (L2-resident). Lane l handles channels [8l, 8(l+1)); head = l>>3.
__global__ __launch_bounds__(256)
void gat_agg(const int* __restrict__ offs, const int* __restrict__ srcarr,
             const float4* __restrict__ als4, const float4* __restrict__ ald4,
             const __half* __restrict__ h,
             const float* __restrict__ bias, int act,
             __nv_bfloat16* __restrict__ ohi, __nv_bfloat16* __restrict__ olo)
{
    int w = (blockIdx.x * blockDim.x + threadIdx.x) >> 5;
    int lane = threadIdx.x & 31;
    if (w >= NNODES) return;
    int n = w;
    int head = lane >> 3;
    int beg = offs[n], end = offs[n + 1];
    float4 aldn = ald4[n];
    float4 an = als4[n];
    float4 eself = leaky4_02(make_float4(an.x + aldn.x, an.y + aldn.y,
                                         an.z + aldn.z, an.w + aldn.w));
    // ---- pass 1: segment max ----
    float4 m = eself;
    for (int j = beg + lane; j < end; j += 32) {
        int s = srcarr[j];
        float4 a = als4[s];
        float4 e = leaky4_02(make_float4(a.x + aldn.x, a.y + aldn.y,
                                         a.z + aldn.z, a.w + aldn.w));
        m.x = fmaxf(m.x, e.x); m.y = fmaxf(m.y, e.y);
        m.z = fmaxf(m.z, e.z); m.w = fmaxf(m.w, e.w);
    }
#pragma unroll
    for (int o = 16; o; o >>= 1) {
        m.x = fmaxf(m.x, __shfl_xor_sync(0xFFFFFFFF, m.x, o));
        m.y = fmaxf(m.y, __shfl_xor_sync(0xFFFFFFFF, m.y, o));
        m.z = fmaxf(m.z, __shfl_xor_sync(0xFFFFFFFF, m.z, o));
        m.w = fmaxf(m.w, __shfl_xor_sync(0xFFFFFFFF, m.w, o));
    }
    // ---- pass 2: p, sum, gather-accumulate (one uint4 = 8 halfs per lane) --
    float acc[8] = {0.f, 0.f, 0.f, 0.f, 0.f, 0.f, 0.f, 0.f};
    float4 psum = make_float4(0.f, 0.f, 0.f, 0.f);
    for (int base = beg; base < end; base += 32) {
        int j = base + lane;
        int valid = j < end;
        int s = valid ? srcarr[j] : 0;
        float4 p = make_float4(0.f, 0.f, 0.f, 0.f);
        if (valid) {
            float4 a = als4[s];
            float4 e = leaky4_02(make_float4(a.x + aldn.x, a.y + aldn.y,
                                             a.z + aldn.z, a.w + aldn.w));
            p.x = __expf(e.x - m.x); p.y = __expf(e.y - m.y);
            p.z = __expf(e.z - m.z); p.w = __expf(e.w - m.w);
            psum.x += p.x; psum.y += p.y; psum.z += p.z; psum.w += p.w;
        }
        int cnt = end - base; if (cnt > 32) cnt = 32;
        for (int jj = 0; jj < cnt; jj++) {
            int   sj = __shfl_sync(0xFFFFFFFF, s, jj);
            float px = __shfl_sync(0xFFFFFFFF, p.x, jj);
            float py = __shfl_sync(0xFFFFFFFF, p.y, jj);
            float pz = __shfl_sync(0xFFFFFFFF, p.z, jj);
            float pw = __shfl_sync(0xFFFFFFFF, p.w, jj);
            float pv = (head == 0) ? px : (head == 1) ? py : (head == 2) ? pz : pw;
            uint4 raw = __ldg((const uint4*)(h + (size_t)sj * HC) + lane);
            float2 f0 = __half22float2(*(__half2*)&raw.x);
            float2 f1 = __half22float2(*(__half2*)&raw.y);
            float2 f2 = __half22float2(*(__half2*)&raw.z);
            float2 f3 = __half22float2(*(__half2*)&raw.w);
            acc[0] += pv * f0.x; acc[1] += pv * f0.y;
            acc[2] += pv * f1.x; acc[3] += pv * f1.y;
            acc[4] += pv * f2.x; acc[5] += pv * f2.y;
            acc[6] += pv * f3.x; acc[7] += pv * f3.y;
        }
    }
#pragma unroll
    for (int o = 16; o; o >>= 1) {
        psum.x += __shfl_xor_sync(0xFFFFFFFF, psum.x, o);
        psum.y += __shfl_xor_sync(0xFFFFFFFF, psum.y, o);
        psum.z += __shfl_xor_sync(0xFFFFFFFF, psum.z, o);
        psum.w += __shfl_xor_sync(0xFFFFFFFF, psum.w, o);
    }
    // self loop contribution
    float4 ps;
    ps.x = __expf(eself.x - m.x); ps.y = __expf(eself.y - m.y);
    ps.z = __expf(eself.z - m.z); ps.w = __expf(eself.w - m.w);
    psum.x += ps.x; psum.y += ps.y; psum.z += ps.z; psum.w += ps.w;
    {
        float pv = (head == 0) ? ps.x : (head == 1) ? ps.y : (head == 2) ? ps.z : ps.w;
        uint4 raw = __ldg((const uint4*)(h + (size_t)n * HC) + lane);
        float2 f0 = __half22float2(*(__half2*)&raw.x);
        float2 f1 = __half22float2(*(__half2*)&raw.y);
        float2 f2 = __half22float2(*(__half2*)&raw.z);
        float2 f3 = __half22float2(*(__half2*)&raw.w);
        acc[0] += pv * f0.x; acc[1] += pv * f0.y;
        acc[2] += pv * f1.x; acc[3] += pv * f1.y;
        acc[4] += pv * f2.x; acc[5] += pv * f2.y;
        acc[6] += pv * f3.x; acc[7] += pv * f3.y;
    }
    // ---- epilogue: divide, bias, act, write bf16 hi/lo ----
    float sH = (head == 0) ? psum.x : (head == 1) ? psum.y : (head == 2) ? psum.z : psum.w;
    float r = 1.f / sH;
    const float4* b4 = (const float4*)bias;   // channels 8l..8l+8 = b4[2l], b4[2l+1]
    float4 bA = b4[lane * 2], bB = b4[lane * 2 + 1];
    float v[8];
    v[0] = acc[0] * r + bA.x; v[1] = acc[1] * r + bA.y;
    v[2] = acc[2] * r + bA.z; v[3] = acc[3] * r + bA.w;
    v[4] = acc[4] * r + bB.x; v[5] = acc[5] * r + bB.y;
    v[6] = acc[6] * r + bB.z; v[7] = acc[7] * r + bB.w;
    if (act) {
#pragma unroll
        for (int q = 0; q < 8; q++) v[q] = v[q] > 0.f ? v[q] : 0.01f * v[q];
    }
    size_t ix = (size_t)n * HC + lane * 8;
    __nv_bfloat162 hi01(__float2bfloat16(v[0]), __float2bfloat16(v[1]));
    __nv_bfloat162 hi23(__float2bfloat16(v[2]), __float2bfloat16(v[3]));
    __nv_bfloat162 hi45(__float2bfloat16(v[4]), __float2bfloat16(v[5]));
    __nv_bfloat162 hi67(__float2bfloat16(v[6]), __float2bfloat16(v[7]));
    *(__nv_bfloat162*)(ohi + ix)     = hi01;
    *(__nv_bfloat162*)(ohi + ix + 2) = hi23;
    *(__nv_bfloat162*)(ohi + ix + 4) = hi45;
    *(__nv_bfloat162*)(ohi + ix + 6) = hi67;
    __nv_bfloat162 lo01(__float2bfloat16(v[0] - __bfloat162float(hi01.x)),
                        __float2bfloat16(v[1] - __bfloat162float(hi01.y)));
    __nv_bfloat162 lo23(__float2bfloat16(v[2] - __bfloat162float(hi23.x)),
                        __float2bfloat16(v[3] - __bfloat162float(hi23.y)));
    __nv_bfloat162 lo45(__float2bfloat16(v[4] - __bfloat162float(hi45.x)),
                        __float2bfloat16(v[5] - __bfloat162float(hi45.y)));
    __nv_bfloat162 lo67(__float2bfloat16(v[6] - __bfloat162float(hi67.x)),
                        __float2bfloat16(v[7] - __bfloat162float(hi67.y)));
    *(__nv_bfloat162*)(olo + ix)     = lo01;
    *(__nv_bfloat162*)(olo + ix + 2) = lo23;
    *(__nv_bfloat162*)(olo + ix + 4) = lo45;
    *(__nv_bfloat162*)(olo + ix + 6) = lo67;
}

// ======================= host orchestration ================================
#define SMEM_N8  (2 * (32768 + 2 * 256 * 128))   // 196608
#define SMEM_N4  (2 * (32768 + 2 * 128 * 128))   // 131072

extern "C" void kernel_launch(void* const* d_in, const int* in_sizes, int n_in,
                              void* d_out, int out_size)
{
    const float* x    = (const float*)d_in[0];
    const void*  ei   = d_in[1];
    const float* root = (const float*)d_in[2];
    const float* W[3]  = {(const float*)d_in[3], (const float*)d_in[7],  (const float*)d_in[11]};
    const float* aS[3] = {(const float*)d_in[4], (const float*)d_in[8],  (const float*)d_in[12]};
    const float* aD[3] = {(const float*)d_in[5], (const float*)d_in[9],  (const float*)d_in[13]};
    const float* bb[3] = {(const float*)d_in[6], (const float*)d_in[10], (const float*)d_in[14]};
    const float* fc_w = (const float*)d_in[15];
    const float* fc_b = (const float*)d_in[16];
    const float* r_w1 = (const float*)d_in[17];
    const float* r_b1 = (const float*)d_in[18];
    const float* r_w2 = (const float*)d_in[19];
    const float* r_b2 = (const float*)d_in[20];
    const float* r_w3 = (const float*)d_in[21];
    const float* r_b3 = (const float*)d_in[22];

    float *p_als, *p_ald;
    __half* p_h;
    int *p_off, *p_cur, *p_srcarr, *p_flag;
    __nv_bfloat16 *p_Ahi, *p_Alo, *p_Bhi, *p_Blo, *p_rAh, *p_rAl, *p_r1h, *p_r1l, *p_r2h, *p_r2l;
    cudaGetSymbolAddress((void**)&p_h,   g_h);
    cudaGetSymbolAddress((void**)&p_als, g_als);
    cudaGetSymbolAddress((void**)&p_ald, g_ald);
    cudaGetSymbolAddress((void**)&p_off, g_off);
    cudaGetSymbolAddress((void**)&p_cur, g_cur);
    cudaGetSymbolAddress((void**)&p_srcarr, g_srcarr);
    cudaGetSymbolAddress((void**)&p_flag, g_is32);
    cudaGetSymbolAddress((void**)&p_Ahi, g_Ahi);
    cudaGetSymbolAddress((void**)&p_Alo, g_Alo);
    cudaGetSymbolAddress((void**)&p_Bhi, g_Bhi);
    cudaGetSymbolAddress((void**)&p_Blo, g_Blo);
    cudaGetSymbolAddress((void**)&p_rAh, g_rAh);
    cudaGetSymbolAddress((void**)&p_rAl, g_rAl);
    cudaGetSymbolAddress((void**)&p_r1h, g_r1h);
    cudaGetSymbolAddress((void**)&p_r1l, g_r1l);
    cudaGetSymbolAddress((void**)&p_r2h, g_r2h);
    cudaGetSymbolAddress((void**)&p_r2l, g_r2l);

    static int smem_set = 0;
    if (!smem_set) {
        cudaFuncSetAttribute(gemm_mma<8>, cudaFuncAttributeMaxDynamicSharedMemorySize, SMEM_N8);
        cudaFuncSetAttribute(gemm_mma<4>, cudaFuncAttributeMaxDynamicSharedMemorySize, SMEM_N4);
        smem_set = 1;
    }

    // ---- CSR build (once per call, reused by all 3 layers) ----
    cudaMemsetAsync(p_flag, 0, sizeof(int));
    detect_idx_kernel<<<(NEDGES + 255) / 256, 256>>>((const long long*)ei, p_flag);
    cudaMemsetAsync(p_cur, 0, NNODES * sizeof(int));
    hist_kernel<<<(NEDGES + 255) / 256, 256>>>(ei, p_flag, p_cur);
    scan_kernel<<<1, 1024>>>(p_cur, p_off);
    scatter_kernel<<<(NEDGES + 255) / 256, 256>>>(ei, p_flag, p_cur, p_srcarr);

    // ---- weight conversions ----
    conv_B_kernel<<<(256 * 128 + 255) / 256, 256>>>(W[0], p_Bhi + OFF_W0, p_Blo + OFF_W0, 80, 256, 128, 256);
    conv_B_kernel<<<(256 * 256 + 255) / 256, 256>>>(W[1], p_Bhi + OFF_W1, p_Blo + OFF_W1, 256, 256, 256, 256);
    conv_B_kernel<<<(256 * 256 + 255) / 256, 256>>>(W[2], p_Bhi + OFF_W2, p_Blo + OFF_W2, 256, 256, 256, 256);
    conv_B_kernel<<<(128 * 256 + 255) / 256, 256>>>(fc_w, p_Bhi + OFF_FC, p_Blo + OFF_FC, 256, 80, 256, 128);
    conv_B_kernel<<<(512 * 64 + 255) / 256, 256>>>(r_w1, p_Bhi + OFF_R1, p_Blo + OFF_R1, 60, 512, 64, 512);
    conv_B_kernel<<<(512 * 512 + 255) / 256, 256>>>(r_w2, p_Bhi + OFF_R2, p_Blo + OFF_R2, 512, 512, 512, 512);
    conv_B_kernel<<<(128 * 512 + 255) / 256, 256>>>(r_w3, p_Bhi + OFF_R3, p_Blo + OFF_R3, 512, 60, 512, 128);

    // x -> bf16 hi/lo, K padded 80->128
    conv_A_kernel<<<(NNODES * 128 + 255) / 256, 256>>>(x, p_Ahi, p_Alo, NNODES, 80, 128);

    const int Kpad[3] = {128, 256, 256};
    const __nv_bfloat16* Boff_hi[3] = {p_Bhi + OFF_W0, p_Bhi + OFF_W1, p_Bhi + OFF_W2};
    const __nv_bfloat16* Boff_lo[3] = {p_Blo + OFF_W0, p_Blo + OFF_W1, p_Blo + OFF_W2};

    for (int L = 0; L < 3; L++) {
        gemm_mma<8><<<dim3(NNODES / 128, 1), 512, SMEM_N8>>>(
            p_Ahi, p_Alo, Kpad[L], Boff_hi[L], Boff_lo[L],
            nullptr, p_h, 256, 256, nullptr, nullptr, 0,
            nullptr, 0, aS[L], aD[L], p_als, p_ald);
        int act = (L < 2) ? 1 : 0;
        gat_agg<<<NNODES / 8, 256>>>(p_off, p_srcarr,
                                     (const float4*)p_als, (const float4*)p_ald,
                                     p_h, bb[L], act, p_Ahi, p_Alo);
    }

    // rot = h @ fc_w + fc_b -> d_out[0 : N*80]  (NBLK=128, only 80 valid)
    float* rot = (float*)d_out;
    gemm_mma<4><<<dim3(NNODES / 128, 1), 512, SMEM_N4>>>(
        p_Ahi, p_Alo, 256, p_Bhi + OFF_FC, p_Blo + OFF_FC,
        rot, nullptr, 80, 80, nullptr, nullptr, 0,
        fc_b, 0, nullptr, nullptr, nullptr, nullptr);

    // root MLP
    conv_A_kernel<<<(4096 * 64 + 255) / 256, 256>>>(root, p_rAh, p_rAl, 4096, 60, 64);
    gemm_mma<8><<<dim3(32, 2), 512, SMEM_N8>>>(
        p_rAh, p_rAl, 64, p_Bhi + OFF_R1, p_Blo + OFF_R1,
        nullptr, nullptr, 512, 512, p_r1h, p_r1l, 512,
        r_b1, 1, nullptr, nullptr, nullptr, nullptr);
    gemm_mma<8><<<dim3(32, 2), 512, SMEM_N8>>>(
        p_r1h, p_r1l, 512, p_Bhi + OFF_R2, p_Blo + OFF_R2,
        nullptr, nullptr, 512, 512, p_r2h, p_r2l, 512,
        r_b2, 1, nullptr, nullptr, nullptr, nullptr);
    float* root_out = rot + (size_t)NNODES * 80;
    gemm_mma<4><<<dim3(32, 1), 512, SMEM_N4>>>(
        p_r2h, p_r2l, 512, p_Bhi + OFF_R3, p_Blo + OFF_R3,
        root_out, nullptr, 60, 60, nullptr, nullptr, 0,
        r_b3, 0, nullptr, nullptr, nullptr, nullptr);
}

// round 9
// speedup vs baseline: 1.5602x; 1.3448x over previous
#include <cuda_runtime.h>
#include <cuda_fp16.h>
#include <cstdint>
#include <math.h>

// Problem constants (fixed by the dataset)
#define NNODES 102400
#define NEDGES 409600
#define HC 256
#define NH 4

// ======================= small helpers =====================================
__device__ __forceinline__ uint32_t smem_to_u32(const void* p) {
    uint32_t a;
    asm("{ .reg .u64 t; cvta.to.shared.u64 t, %1; cvt.u32.u64 %0, t; }" : "=r"(a) : "l"(p));
    return a;
}
__device__ __forceinline__ void cp16(uint32_t s, const void* g) {
    asm volatile("cp.async.cg.shared.global [%0], [%1], 16;" :: "r"(s), "l"(g));
}
__device__ __forceinline__ uint32_t lds32(uint32_t a) {
    uint32_t v; asm volatile("ld.shared.b32 %0, [%1];" : "=r"(v) : "r"(a)); return v;
}
__device__ __forceinline__ uint32_t smaddr(uint32_t base, int r, int c) {
    return base + r * 128 + ((((c >> 2) ^ (r & 7)) << 4)) + ((c & 3) << 2);
}
__device__ __forceinline__ void mma_f16(float* d, uint32_t a0, uint32_t a1, uint32_t a2,
                                        uint32_t a3, uint32_t b0, uint32_t b1) {
    asm volatile(
        "mma.sync.aligned.m16n8k16.row.col.f32.f16.f16.f32 "
        "{%0,%1,%2,%3}, {%4,%5,%6,%7}, {%8,%9}, {%0,%1,%2,%3};"
        : "+f"(d[0]), "+f"(d[1]), "+f"(d[2]), "+f"(d[3])
        : "r"(a0), "r"(a1), "r"(a2), "r"(a3), "r"(b0), "r"(b1));
}
__device__ __forceinline__ float4 leaky4_02(float4 v) {
    v.x = v.x > 0.f ? v.x : 0.2f * v.x;
    v.y = v.y > 0.f ? v.y : 0.2f * v.y;
    v.z = v.z > 0.f ? v.z : 0.2f * v.z;
    v.w = v.w > 0.f ? v.w : 0.2f * v.w;
    return v;
}

// ======================= scratch (device globals) ==========================
__device__ __align__(16) __half g_h[(size_t)NNODES * HC];   // W-transformed feats
__device__ __align__(16) __half g_A[(size_t)NNODES * HC];   // layer input (aggregated)
__device__ __align__(16) float g_als[NNODES * NH];
__device__ __align__(16) float g_ald[NNODES * NH];
__device__ int g_off[NNODES + 1];
__device__ int g_cur[NNODES];
__device__ int g_srcarr[NEDGES];
__device__ int g_is32;
__device__ __align__(16) __half g_B[600000];
__device__ __align__(16) __half g_rA[4096 * 64];
__device__ __align__(16) __half g_r1[4096 * 512];
__device__ __align__(16) __half g_r2[4096 * 512];

// B buffer element offsets (B stored [Npad][Kpad], zero padded)
#define OFF_W0  0        // 256 x 128
#define OFF_W1  32768    // 256 x 256
#define OFF_W2  98304    // 256 x 256
#define OFF_FC  163840   // 128 x 256
#define OFF_R1  196608   // 512 x 64
#define OFF_R2  229376   // 512 x 512
#define OFF_R3  491520   // 128 x 512

// ======================= edge utilities ====================================
__device__ __forceinline__ void load_edge(const void* ei, int is32, int idx,
                                          int& src, int& dst) {
    if (is32) {
        src = ((const int*)ei)[idx];
        dst = ((const int*)ei)[NEDGES + idx];
    } else {
        src = (int)((const long long*)ei)[idx];
        dst = (int)((const long long*)ei)[NEDGES + idx];
    }
}

__global__ void detect_idx_kernel(const long long* ei, int* flag) {
    int i = blockIdx.x * blockDim.x + threadIdx.x;
    if (i >= NEDGES) return;
    long long v = ei[i];
    if (v < 0 || v >= (long long)NNODES) atomicOr(flag, 1);
}

__global__ void hist_kernel(const void* __restrict__ ei, const int* __restrict__ flag,
                            int* __restrict__ counts) {
    int i = blockIdx.x * blockDim.x + threadIdx.x;
    if (i >= NEDGES) return;
    int s, d;
    load_edge(ei, *flag, i, s, d);
    atomicAdd(&counts[d], 1);
}

// single block, 1024 threads, 100 counts each (1024*100 == NNODES)
__global__ void scan_kernel(int* __restrict__ counts_cursor, int* __restrict__ offs) {
    __shared__ int part[1024];
    int t = threadIdx.x;
    int base = t * 100;
    int sum = 0;
    for (int i = 0; i < 100; i++) sum += counts_cursor[base + i];
    part[t] = sum;
    __syncthreads();
    for (int d = 1; d < 1024; d <<= 1) {
        int v = (t >= d) ? part[t - d] : 0;
        __syncthreads();
        part[t] += v;
        __syncthreads();
    }
    int run = (t == 0) ? 0 : part[t - 1];
    for (int i = 0; i < 100; i++) {
        int c = counts_cursor[base + i];
        offs[base + i] = run;
        counts_cursor[base + i] = run;   // cursor for scatter
        run += c;
    }
    if (t == 1023) offs[NNODES] = run;
}

__global__ void scatter_kernel(const void* __restrict__ ei, const int* __restrict__ flag,
                               int* __restrict__ cursor, int* __restrict__ srcarr) {
    int i = blockIdx.x * blockDim.x + threadIdx.x;
    if (i >= NEDGES) return;
    int s, d;
    load_edge(ei, *flag, i, s, d);
    int pos = atomicAdd(&cursor[d], 1);
    srcarr[pos] = s;
}

// ======================= misc conversions ==================================
__global__ void conv_A_kernel(const float* __restrict__ A, __half* __restrict__ out,
                              int M, int K, int Kpad) {
    int i = blockIdx.x * blockDim.x + threadIdx.x;
    if (i >= M * Kpad) return;
    int m = i / Kpad, k = i - m * Kpad;
    float v = (k < K) ? A[(size_t)m * K + k] : 0.f;
    out[i] = __float2half(v);
}

// B [K,N] fp32 row-major -> Bt [Npad, Kpad] fp16 (zero padded)
__global__ void conv_B_kernel(const float* __restrict__ B, __half* __restrict__ out,
                              int K, int N, int Kpad, int Npad) {
    int i = blockIdx.x * blockDim.x + threadIdx.x;
    if (i >= Npad * Kpad) return;
    int n = i / Kpad, k = i - n * Kpad;
    float v = (k < K && n < N) ? B[(size_t)k * N + n] : 0.f;
    out[i] = __float2half(v);
}

// ======================= fp16 mma.sync GEMM ================================
// 512 threads = 16 warps (4 warpM x 4 warpN), warp tile 32 x (N8*8).
// CTA tile 128 x NBLK (NBLK = N8*32). K chunks of 64, double buffered.
// N8=8: NBLK=256 (layer GEMMs, fused attn logits). N8=4: NBLK=128 (fc, r3).
template<int N8>
__global__ __launch_bounds__(512, 1)
void gemm_mma(const __half* __restrict__ A, int Kpad, const __half* __restrict__ B,
              float* outf, __half* outh, int nwrite, int ldout,
              const float* __restrict__ bias, int act,
              const float* __restrict__ a_src, const float* __restrict__ a_dst,
              float* als, float* ald)
{
    constexpr int NBLK = N8 * 32;
    constexpr uint32_t ASTAGE = 16384u;                 // 128 rows x 128B
    constexpr uint32_t BSTAGE = (uint32_t)NBLK * 128u;
    constexpr uint32_t STAGE = ASTAGE + BSTAGE;
    extern __shared__ char sm_raw[];
    uint32_t sb = smem_to_u32(sm_raw);
    int tid = threadIdx.x, wid = tid >> 5, lane = tid & 31;
    int warpM = wid & 3, warpN = wid >> 2;
    int mBase = blockIdx.x * 128;
    int nBase = blockIdx.y * NBLK;
    const int NC = Kpad >> 6;
    const int kp = lane & 3;
    const int lq = lane >> 2;

    float acc[2][N8][4];
#pragma unroll
    for (int i = 0; i < 2; i++)
#pragma unroll
        for (int j = 0; j < N8; j++)
#pragma unroll
            for (int q = 0; q < 4; q++) acc[i][j][q] = 0.f;

    // ---- prologue: stage 0 ----
    {
        uint32_t base = sb;
#pragma unroll
        for (int i = 0; i < 2; i++) {                 // A: 1024 granules
            int u = tid + i * 512;
            int row = u >> 3, g = u & 7;
            const __half* src = A + (size_t)(mBase + row) * Kpad + g * 8;
            cp16(base + row * 128 + (((g ^ (row & 7)) << 4)), src);
        }
        for (int u = tid; u < NBLK * 8; u += 512) {   // B granules
            int row = u >> 3, g = u & 7;
            const __half* src = B + (size_t)(nBase + row) * Kpad + g * 8;
            cp16(base + ASTAGE + row * 128 + (((g ^ (row & 7)) << 4)), src);
        }
        asm volatile("cp.async.commit_group;" ::: "memory");
    }

    for (int c = 0; c < NC; c++) {
        if (c + 1 < NC) {
            uint32_t base = sb + ((c + 1) & 1) * STAGE;
            int ko = (c + 1) * 64;
#pragma unroll
            for (int i = 0; i < 2; i++) {
                int u = tid + i * 512;
                int row = u >> 3, g = u & 7;
                const __half* src = A + (size_t)(mBase + row) * Kpad + ko + g * 8;
                cp16(base + row * 128 + (((g ^ (row & 7)) << 4)), src);
            }
            for (int u = tid; u < NBLK * 8; u += 512) {
                int row = u >> 3, g = u & 7;
                const __half* src = B + (size_t)(nBase + row) * Kpad + ko + g * 8;
                cp16(base + ASTAGE + row * 128 + (((g ^ (row & 7)) << 4)), src);
            }
            asm volatile("cp.async.commit_group;" ::: "memory");
            asm volatile("cp.async.wait_group 1;" ::: "memory");
        } else {
            asm volatile("cp.async.wait_group 0;" ::: "memory");
        }
        __syncthreads();

        uint32_t aB = sb + (c & 1) * STAGE;
        uint32_t bB = aB + ASTAGE;
#pragma unroll
        for (int k16 = 0; k16 < 4; k16++) {
            int c0 = k16 * 8;
            uint32_t Af[2][4];
#pragma unroll
            for (int mf = 0; mf < 2; mf++) {
                int r0 = warpM * 32 + mf * 16 + lq;
                Af[mf][0] = lds32(smaddr(aB, r0,     c0 + kp));
                Af[mf][1] = lds32(smaddr(aB, r0 + 8, c0 + kp));
                Af[mf][2] = lds32(smaddr(aB, r0,     c0 + kp + 4));
                Af[mf][3] = lds32(smaddr(aB, r0 + 8, c0 + kp + 4));
            }
#pragma unroll
            for (int n8 = 0; n8 < N8; n8++) {
                int n = warpN * N8 * 8 + n8 * 8 + lq;
                uint32_t b0 = lds32(smaddr(bB, n, c0 + kp));
                uint32_t b1 = lds32(smaddr(bB, n, c0 + kp + 4));
#pragma unroll
                for (int mf = 0; mf < 2; mf++)
                    mma_f16(acc[mf][n8], Af[mf][0], Af[mf][1], Af[mf][2], Af[mf][3], b0, b1);
            }
        }
        __syncthreads();
    }

    // ---- epilogue ----
    int limit = nwrite - nBase;
    float s1[2][2] = {{0.f, 0.f}, {0.f, 0.f}};
    float s2[2][2] = {{0.f, 0.f}, {0.f, 0.f}};
#pragma unroll
    for (int mf = 0; mf < 2; mf++) {
        int gr0 = mBase + warpM * 32 + mf * 16 + lq;
#pragma unroll
        for (int n8 = 0; n8 < N8; n8++) {
            int cl = warpN * N8 * 8 + n8 * 8 + kp * 2;
            float v[4];
#pragma unroll
            for (int q = 0; q < 4; q++) v[q] = acc[mf][n8][q];
#pragma unroll
            for (int q = 0; q < 4; q++) {
                int col = cl + (q & 1);
                if (col < limit) {
                    float x = v[q];
                    if (bias) x += bias[nBase + col];
                    if (act) x = x > 0.f ? x : 0.01f * x;
                    v[q] = x;
                }
            }
            if (a_src) {
                s1[mf][0] += v[0] * a_src[cl] + v[1] * a_src[cl + 1];
                s2[mf][0] += v[0] * a_dst[cl] + v[1] * a_dst[cl + 1];
                s1[mf][1] += v[2] * a_src[cl] + v[3] * a_src[cl + 1];
                s2[mf][1] += v[2] * a_dst[cl] + v[3] * a_dst[cl + 1];
            }
            if (outf) {
                if (cl + 1 < limit) {
                    *(float2*)(outf + (size_t)gr0 * ldout + nBase + cl) = make_float2(v[0], v[1]);
                    *(float2*)(outf + (size_t)(gr0 + 8) * ldout + nBase + cl) = make_float2(v[2], v[3]);
                } else if (cl < limit) {
                    outf[(size_t)gr0 * ldout + nBase + cl] = v[0];
                    outf[(size_t)(gr0 + 8) * ldout + nBase + cl] = v[2];
                }
            }
            if (outh && cl < limit) {
                *(__half2*)(outh + (size_t)gr0 * ldout + nBase + cl) = __floats2half2_rn(v[0], v[1]);
                *(__half2*)(outh + (size_t)(gr0 + 8) * ldout + nBase + cl) = __floats2half2_rn(v[2], v[3]);
            }
        }
    }
    if (a_src) {
        // warpN == head (N8 == 8: warp covers 64 cols == one head)
#pragma unroll
        for (int mf = 0; mf < 2; mf++)
#pragma unroll
            for (int hf = 0; hf < 2; hf++) {
                s1[mf][hf] += __shfl_xor_sync(0xFFFFFFFF, s1[mf][hf], 1);
                s1[mf][hf] += __shfl_xor_sync(0xFFFFFFFF, s1[mf][hf], 2);
                s2[mf][hf] += __shfl_xor_sync(0xFFFFFFFF, s2[mf][hf], 1);
                s2[mf][hf] += __shfl_xor_sync(0xFFFFFFFF, s2[mf][hf], 2);
            }
        if ((lane & 3) == 0) {
#pragma unroll
            for (int mf = 0; mf < 2; mf++)
#pragma unroll
                for (int hf = 0; hf < 2; hf++) {
                    int gr = mBase + warpM * 32 + mf * 16 + hf * 8 + lq;
                    als[gr * 4 + warpN] = s1[mf][hf];
                    ald[gr * 4 + warpN] = s2[mf][hf];
                }
        }
    }
}

// ======================= fused GAT aggregation (one warp per dst) ==========
// h is fp16 (L2-resident). Lane l handles channels [8l, 8(l+1)); head = l>>3.
// Output written as fp16 (next layer's GEMM A operand).
__global__ __launch_bounds__(256)
void gat_agg(const int* __restrict__ offs, const int* __restrict__ srcarr,
             const float4* __restrict__ als4, const float4* __restrict__ ald4,
             const __half* __restrict__ h,
             const float* __restrict__ bias, int act,
             __half* __restrict__ out)
{
    int w = (blockIdx.x * blockDim.x + threadIdx.x) >> 5;
    int lane = threadIdx.x & 31;
    if (w >= NNODES) return;
    int n = w;
    int head = lane >> 3;
    int beg = offs[n], end = offs[n + 1];
    float4 aldn = ald4[n];
    float4 an = als4[n];
    float4 eself = leaky4_02(make_float4(an.x + aldn.x, an.y + aldn.y,
                                         an.z + aldn.z, an.w + aldn.w));
    // ---- pass 1: segment max ----
    float4 m = eself;
    for (int j = beg + lane; j < end; j += 32) {
        int s = srcarr[j];
        float4 a = als4[s];
        float4 e = leaky4_02(make_float4(a.x + aldn.x, a.y + aldn.y,
                                         a.z + aldn.z, a.w + aldn.w));
        m.x = fmaxf(m.x, e.x); m.y = fmaxf(m.y, e.y);
        m.z = fmaxf(m.z, e.z); m.w = fmaxf(m.w, e.w);
    }
#pragma unroll
    for (int o = 16; o; o >>= 1) {
        m.x = fmaxf(m.x, __shfl_xor_sync(0xFFFFFFFF, m.x, o));
        m.y = fmaxf(m.y, __shfl_xor_sync(0xFFFFFFFF, m.y, o));
        m.z = fmaxf(m.z, __shfl_xor_sync(0xFFFFFFFF, m.z, o));
        m.w = fmaxf(m.w, __shfl_xor_sync(0xFFFFFFFF, m.w, o));
    }
    // ---- pass 2: p, sum, gather-accumulate (one uint4 = 8 halfs per lane) --
    float acc[8] = {0.f, 0.f, 0.f, 0.f, 0.f, 0.f, 0.f, 0.f};
    float4 psum = make_float4(0.f, 0.f, 0.f, 0.f);
    for (int base = beg; base < end; base += 32) {
        int j = base + lane;
        int valid = j < end;
        int s = valid ? srcarr[j] : 0;
        float4 p = make_float4(0.f, 0.f, 0.f, 0.f);
        if (valid) {
            float4 a = als4[s];
            float4 e = leaky4_02(make_float4(a.x + aldn.x, a.y + aldn.y,
                                             a.z + aldn.z, a.w + aldn.w));
            p.x = __expf(e.x - m.x); p.y = __expf(e.y - m.y);
            p.z = __expf(e.z - m.z); p.w = __expf(e.w - m.w);
            psum.x += p.x; psum.y += p.y; psum.z += p.z; psum.w += p.w;
        }
        int cnt = end - base; if (cnt > 32) cnt = 32;
        for (int jj = 0; jj < cnt; jj++) {
            int   sj = __shfl_sync(0xFFFFFFFF, s, jj);
            float px = __shfl_sync(0xFFFFFFFF, p.x, jj);
            float py = __shfl_sync(0xFFFFFFFF, p.y, jj);
            float pz = __shfl_sync(0xFFFFFFFF, p.z, jj);
            float pw = __shfl_sync(0xFFFFFFFF, p.w, jj);
            float pv = (head == 0) ? px : (head == 1) ? py : (head == 2) ? pz : pw;
            uint4 raw = __ldg((const uint4*)(h + (size_t)sj * HC) + lane);
            float2 f0 = __half22float2(*(__half2*)&raw.x);
            float2 f1 = __half22float2(*(__half2*)&raw.y);
            float2 f2 = __half22float2(*(__half2*)&raw.z);
            float2 f3 = __half22float2(*(__half2*)&raw.w);
            acc[0] += pv * f0.x; acc[1] += pv * f0.y;
            acc[2] += pv * f1.x; acc[3] += pv * f1.y;
            acc[4] += pv * f2.x; acc[5] += pv * f2.y;
            acc[6] += pv * f3.x; acc[7] += pv * f3.y;
        }
    }
#pragma unroll
    for (int o = 16; o; o >>= 1) {
        psum.x += __shfl_xor_sync(0xFFFFFFFF, psum.x, o);
        psum.y += __shfl_xor_sync(0xFFFFFFFF, psum.y, o);
        psum.z += __shfl_xor_sync(0xFFFFFFFF, psum.z, o);
        psum.w += __shfl_xor_sync(0xFFFFFFFF, psum.w, o);
    }
    // self loop contribution
    float4 ps;
    ps.x = __expf(eself.x - m.x); ps.y = __expf(eself.y - m.y);
    ps.z = __expf(eself.z - m.z); ps.w = __expf(eself.w - m.w);
    psum.x += ps.x; psum.y += ps.y; psum.z += ps.z; psum.w += ps.w;
    {
        float pv = (head == 0) ? ps.x : (head == 1) ? ps.y : (head == 2) ? ps.z : ps.w;
        uint4 raw = __ldg((const uint4*)(h + (size_t)n * HC) + lane);
        float2 f0 = __half22float2(*(__half2*)&raw.x);
        float2 f1 = __half22float2(*(__half2*)&raw.y);
        float2 f2 = __half22float2(*(__half2*)&raw.z);
        float2 f3 = __half22float2(*(__half2*)&raw.w);
        acc[0] += pv * f0.x; acc[1] += pv * f0.y;
        acc[2] += pv * f1.x; acc[3] += pv * f1.y;
        acc[4] += pv * f2.x; acc[5] += pv * f2.y;
        acc[6] += pv * f3.x; acc[7] += pv * f3.y;
    }
    // ---- epilogue: divide, bias, act, write fp16 ----
    float sH = (head == 0) ? psum.x : (head == 1) ? psum.y : (head == 2) ? psum.z : psum.w;
    float r = 1.f / sH;
    const float4* b4 = (const float4*)bias;   // channels 8l..8l+8 = b4[2l], b4[2l+1]
    float4 bA = b4[lane * 2], bB = b4[lane * 2 + 1];
    float v[8];
    v[0] = acc[0] * r + bA.x; v[1] = acc[1] * r + bA.y;
    v[2] = acc[2] * r + bA.z; v[3] = acc[3] * r + bA.w;
    v[4] = acc[4] * r + bB.x; v[5] = acc[5] * r + bB.y;
    v[6] = acc[6] * r + bB.z; v[7] = acc[7] * r + bB.w;
    if (act) {
#pragma unroll
        for (int q = 0; q < 8; q++) v[q] = v[q] > 0.f ? v[q] : 0.01f * v[q];
    }
    uint4 pack;
    *(__half2*)&pack.x = __floats2half2_rn(v[0], v[1]);
    *(__half2*)&pack.y = __floats2half2_rn(v[2], v[3]);
    *(__half2*)&pack.z = __floats2half2_rn(v[4], v[5]);
    *(__half2*)&pack.w = __floats2half2_rn(v[6], v[7]);
    *((uint4*)(out + (size_t)n * HC) + lane) = pack;
}

// ======================= host orchestration ================================
#define SMEM_N8  (2 * (16384 + 256 * 128))   // 98304
#define SMEM_N4  (2 * (16384 + 128 * 128))   // 65536

extern "C" void kernel_launch(void* const* d_in, const int* in_sizes, int n_in,
                              void* d_out, int out_size)
{
    const float* x    = (const float*)d_in[0];
    const void*  ei   = d_in[1];
    const float* root = (const float*)d_in[2];
    const float* W[3]  = {(const float*)d_in[3], (const float*)d_in[7],  (const float*)d_in[11]};
    const float* aS[3] = {(const float*)d_in[4], (const float*)d_in[8],  (const float*)d_in[12]};
    const float* aD[3] = {(const float*)d_in[5], (const float*)d_in[9],  (const float*)d_in[13]};
    const float* bb[3] = {(const float*)d_in[6], (const float*)d_in[10], (const float*)d_in[14]};
    const float* fc_w = (const float*)d_in[15];
    const float* fc_b = (const float*)d_in[16];
    const float* r_w1 = (const float*)d_in[17];
    const float* r_b1 = (const float*)d_in[18];
    const float* r_w2 = (const float*)d_in[19];
    const float* r_b2 = (const float*)d_in[20];
    const float* r_w3 = (const float*)d_in[21];
    const float* r_b3 = (const float*)d_in[22];

    float *p_als, *p_ald;
    __half *p_h, *p_A, *p_B, *p_rA, *p_r1, *p_r2;
    int *p_off, *p_cur, *p_srcarr, *p_flag;
    cudaGetSymbolAddress((void**)&p_h,   g_h);
    cudaGetSymbolAddress((void**)&p_A,   g_A);
    cudaGetSymbolAddress((void**)&p_als, g_als);
    cudaGetSymbolAddress((void**)&p_ald, g_ald);
    cudaGetSymbolAddress((void**)&p_off, g_off);
    cudaGetSymbolAddress((void**)&p_cur, g_cur);
    cudaGetSymbolAddress((void**)&p_srcarr, g_srcarr);
    cudaGetSymbolAddress((void**)&p_flag, g_is32);
    cudaGetSymbolAddress((void**)&p_B,   g_B);
    cudaGetSymbolAddress((void**)&p_rA,  g_rA);
    cudaGetSymbolAddress((void**)&p_r1,  g_r1);
    cudaGetSymbolAddress((void**)&p_r2,  g_r2);

    static int smem_set = 0;
    if (!smem_set) {
        cudaFuncSetAttribute(gemm_mma<8>, cudaFuncAttributeMaxDynamicSharedMemorySize, SMEM_N8);
        cudaFuncSetAttribute(gemm_mma<4>, cudaFuncAttributeMaxDynamicSharedMemorySize, SMEM_N4);
        smem_set = 1;
    }

    // ---- CSR build (once per call, reused by all 3 layers) ----
    cudaMemsetAsync(p_flag, 0, sizeof(int));
    detect_idx_kernel<<<(NEDGES + 255) / 256, 256>>>((const long long*)ei, p_flag);
    cudaMemsetAsync(p_cur, 0, NNODES * sizeof(int));
    hist_kernel<<<(NEDGES + 255) / 256, 256>>>(ei, p_flag, p_cur);
    scan_kernel<<<1, 1024>>>(p_cur, p_off);
    scatter_kernel<<<(NEDGES + 255) / 256, 256>>>(ei, p_flag, p_cur, p_srcarr);

    // ---- weight conversions ----
    conv_B_kernel<<<(256 * 128 + 255) / 256, 256>>>(W[0], p_B + OFF_W0, 80, 256, 128, 256);
    conv_B_kernel<<<(256 * 256 + 255) / 256, 256>>>(W[1], p_B + OFF_W1, 256, 256, 256, 256);
    conv_B_kernel<<<(256 * 256 + 255) / 256, 256>>>(W[2], p_B + OFF_W2, 256, 256, 256, 256);
    conv_B_kernel<<<(128 * 256 + 255) / 256, 256>>>(fc_w, p_B + OFF_FC, 256, 80, 256, 128);
    conv_B_kernel<<<(512 * 64 + 255) / 256, 256>>>(r_w1, p_B + OFF_R1, 60, 512, 64, 512);
    conv_B_kernel<<<(512 * 512 + 255) / 256, 256>>>(r_w2, p_B + OFF_R2, 512, 512, 512, 512);
    conv_B_kernel<<<(128 * 512 + 255) / 256, 256>>>(r_w3, p_B + OFF_R3, 512, 60, 512, 128);

    // x -> fp16, K padded 80->128
    conv_A_kernel<<<(NNODES * 128 + 255) / 256, 256>>>(x, p_A, NNODES, 80, 128);

    const int Kpad[3] = {128, 256, 256};
    const __half* Boff[3] = {p_B + OFF_W0, p_B + OFF_W1, p_B + OFF_W2};

    for (int L = 0; L < 3; L++) {
        gemm_mma<8><<<dim3(NNODES / 128, 1), 512, SMEM_N8>>>(
            p_A, Kpad[L], Boff[L],
            nullptr, p_h, 256, 256,
            nullptr, 0, aS[L], aD[L], p_als, p_ald);
        int act = (L < 2) ? 1 : 0;
        gat_agg<<<NNODES / 8, 256>>>(p_off, p_srcarr,
                                     (const float4*)p_als, (const float4*)p_ald,
                                     p_h, bb[L], act, p_A);
    }

    // rot = h @ fc_w + fc_b -> d_out[0 : N*80]  (NBLK=128, only 80 valid)
    float* rot = (float*)d_out;
    gemm_mma<4><<<dim3(NNODES / 128, 1), 512, SMEM_N4>>>(
        p_A, 256, p_B + OFF_FC,
        rot, nullptr, 80, 80,
        fc_b, 0, nullptr, nullptr, nullptr, nullptr);

    // root MLP
    conv_A_kernel<<<(4096 * 64 + 255) / 256, 256>>>(root, p_rA, 4096, 60, 64);
    gemm_mma<8><<<dim3(32, 2), 512, SMEM_N8>>>(
        p_rA, 64, p_B + OFF_R1,
        nullptr, p_r1, 512, 512,
        r_b1, 1, nullptr, nullptr, nullptr, nullptr);
    gemm_mma<8><<<dim3(32, 2), 512, SMEM_N8>>>(
        p_r1, 512, p_B + OFF_R2,
        nullptr, p_r2, 512, 512,
        r_b2, 1, nullptr, nullptr, nullptr, nullptr);
    float* root_out = rot + (size_t)NNODES * 80;
    gemm_mma<4><<<dim3(32, 1), 512, SMEM_N4>>>(
        p_r2, 512, p_B + OFF_R3,
        root_out, nullptr, 60, 60,
        r_b3, 0, nullptr, nullptr, nullptr, nullptr);
}

// round 10
// speedup vs baseline: 1.6201x; 1.0384x over previous
#include <cuda_runtime.h>
#include <cuda_fp16.h>
#include <cstdint>
#include <math.h>

// Problem constants (fixed by the dataset)
#define NNODES 102400
#define NEDGES 409600
#define HC 256
#define NH 4

// ======================= small helpers =====================================
__device__ __forceinline__ uint32_t smem_to_u32(const void* p) {
    uint32_t a;
    asm("{ .reg .u64 t; cvta.to.shared.u64 t, %1; cvt.u32.u64 %0, t; }" : "=r"(a) : "l"(p));
    return a;
}
__device__ __forceinline__ void cp16(uint32_t s, const void* g) {
    asm volatile("cp.async.cg.shared.global [%0], [%1], 16;" :: "r"(s), "l"(g));
}
__device__ __forceinline__ uint32_t lds32(uint32_t a) {
    uint32_t v; asm volatile("ld.shared.b32 %0, [%1];" : "=r"(v) : "r"(a)); return v;
}
__device__ __forceinline__ uint32_t smaddr(uint32_t base, int r, int c) {
    return base + r * 128 + ((((c >> 2) ^ (r & 7)) << 4)) + ((c & 3) << 2);
}
__device__ __forceinline__ void mma_f16(float* d, uint32_t a0, uint32_t a1, uint32_t a2,
                                        uint32_t a3, uint32_t b0, uint32_t b1) {
    asm volatile(
        "mma.sync.aligned.m16n8k16.row.col.f32.f16.f16.f32 "
        "{%0,%1,%2,%3}, {%4,%5,%6,%7}, {%8,%9}, {%0,%1,%2,%3};"
        : "+f"(d[0]), "+f"(d[1]), "+f"(d[2]), "+f"(d[3])
        : "r"(a0), "r"(a1), "r"(a2), "r"(a3), "r"(b0), "r"(b1));
}
__device__ __forceinline__ float4 leaky4_02(float4 v) {
    v.x = v.x > 0.f ? v.x : 0.2f * v.x;
    v.y = v.y > 0.f ? v.y : 0.2f * v.y;
    v.z = v.z > 0.f ? v.z : 0.2f * v.z;
    v.w = v.w > 0.f ? v.w : 0.2f * v.w;
    return v;
}

// ======================= scratch (device globals) ==========================
__device__ __align__(16) __half g_h[(size_t)NNODES * HC];   // W-transformed feats
__device__ __align__(16) __half g_A[(size_t)NNODES * HC];   // layer input (aggregated)
__device__ __align__(16) float g_als[NNODES * NH];
__device__ __align__(16) float g_ald[NNODES * NH];
__device__ int g_off[NNODES + 1];
__device__ int g_cur[NNODES];
__device__ int g_srcarr[NEDGES];
__device__ int g_is32;
__device__ __align__(16) __half g_B[600000];
__device__ __align__(16) __half g_rA[4096 * 64];
__device__ __align__(16) __half g_r1[4096 * 512];
__device__ __align__(16) __half g_r2[4096 * 512];

// B buffer element offsets (B stored [Npad][Kpad], zero padded)
#define OFF_W0  0        // 256 x 128
#define OFF_W1  32768    // 256 x 256
#define OFF_W2  98304    // 256 x 256
#define OFF_FC  163840   // 128 x 256
#define OFF_R1  196608   // 512 x 64
#define OFF_R2  229376   // 512 x 512
#define OFF_R3  491520   // 128 x 512

// ======================= edge utilities ====================================
__device__ __forceinline__ void load_edge(const void* ei, int is32, int idx,
                                          int& src, int& dst) {
    if (is32) {
        src = ((const int*)ei)[idx];
        dst = ((const int*)ei)[NEDGES + idx];
    } else {
        src = (int)((const long long*)ei)[idx];
        dst = (int)((const long long*)ei)[NEDGES + idx];
    }
}

__global__ void detect_idx_kernel(const long long* ei, int* flag) {
    int i = blockIdx.x * blockDim.x + threadIdx.x;
    if (i >= NEDGES) return;
    long long v = ei[i];
    if (v < 0 || v >= (long long)NNODES) atomicOr(flag, 1);
}

__global__ void hist_kernel(const void* __restrict__ ei, const int* __restrict__ flag,
                            int* __restrict__ counts) {
    int i = blockIdx.x * blockDim.x + threadIdx.x;
    if (i >= NEDGES) return;
    int s, d;
    load_edge(ei, *flag, i, s, d);
    atomicAdd(&counts[d], 1);
}

// single block, 1024 threads, 100 counts each (1024*100 == NNODES)
__global__ void scan_kernel(int* __restrict__ counts_cursor, int* __restrict__ offs) {
    __shared__ int part[1024];
    int t = threadIdx.x;
    int base = t * 100;
    int sum = 0;
    for (int i = 0; i < 100; i++) sum += counts_cursor[base + i];
    part[t] = sum;
    __syncthreads();
    for (int d = 1; d < 1024; d <<= 1) {
        int v = (t >= d) ? part[t - d] : 0;
        __syncthreads();
        part[t] += v;
        __syncthreads();
    }
    int run = (t == 0) ? 0 : part[t - 1];
    for (int i = 0; i < 100; i++) {
        int c = counts_cursor[base + i];
        offs[base + i] = run;
        counts_cursor[base + i] = run;   // cursor for scatter
        run += c;
    }
    if (t == 1023) offs[NNODES] = run;
}

__global__ void scatter_kernel(const void* __restrict__ ei, const int* __restrict__ flag,
                               int* __restrict__ cursor, int* __restrict__ srcarr) {
    int i = blockIdx.x * blockDim.x + threadIdx.x;
    if (i >= NEDGES) return;
    int s, d;
    load_edge(ei, *flag, i, s, d);
    int pos = atomicAdd(&cursor[d], 1);
    srcarr[pos] = s;
}

// ======================= misc conversions ==================================
__global__ void conv_A_kernel(const float* __restrict__ A, __half* __restrict__ out,
                              int M, int K, int Kpad) {
    int i = blockIdx.x * blockDim.x + threadIdx.x;
    if (i >= M * Kpad) return;
    int m = i / Kpad, k = i - m * Kpad;
    float v = (k < K) ? A[(size_t)m * K + k] : 0.f;
    out[i] = __float2half(v);
}

// All weight tables converted in ONE launch. B [K,N] fp32 row-major ->
// Bt [Npad, Kpad] fp16 (zero padded), per-segment descriptors.
struct ConvDesc { const float* src; int K, N, Kpad, dstOff, base, elems; };
struct ConvTable { ConvDesc d[7]; int total; };
__global__ void conv_B_all(ConvTable t, __half* __restrict__ out) {
    int i = blockIdx.x * blockDim.x + threadIdx.x;
    if (i >= t.total) return;
    int seg = 0;
#pragma unroll
    for (int q = 0; q < 6; q++)
        if (i >= t.d[q].base + t.d[q].elems) seg = q + 1;
    const ConvDesc& dd = t.d[seg];
    int local = i - dd.base;
    int n = local / dd.Kpad, k = local - n * dd.Kpad;
    float v = (k < dd.K && n < dd.N) ? dd.src[(size_t)k * dd.N + n] : 0.f;
    out[dd.dstOff + local] = __float2half(v);
}

// ======================= fp16 mma.sync GEMM ================================
// 512 threads = 16 warps (4 warpM x 4 warpN), warp tile 32 x (N8*8).
// CTA tile 128 x NBLK (NBLK = N8*32). K chunks of 64, double buffered.
// N8=8: NBLK=256 (layer GEMMs, fused attn logits). N8=4: NBLK=128 (fc, r3).
template<int N8>
__global__ __launch_bounds__(512, 1)
void gemm_mma(const __half* __restrict__ A, int Kpad, const __half* __restrict__ B,
              float* outf, __half* outh, int nwrite, int ldout,
              const float* __restrict__ bias, int act,
              const float* __restrict__ a_src, const float* __restrict__ a_dst,
              float* als, float* ald)
{
    constexpr int NBLK = N8 * 32;
    constexpr uint32_t ASTAGE = 16384u;                 // 128 rows x 128B
    constexpr uint32_t BSTAGE = (uint32_t)NBLK * 128u;
    constexpr uint32_t STAGE = ASTAGE + BSTAGE;
    extern __shared__ char sm_raw[];
    uint32_t sb = smem_to_u32(sm_raw);
    int tid = threadIdx.x, wid = tid >> 5, lane = tid & 31;
    int warpM = wid & 3, warpN = wid >> 2;
    int mBase = blockIdx.x * 128;
    int nBase = blockIdx.y * NBLK;
    const int NC = Kpad >> 6;
    const int kp = lane & 3;
    const int lq = lane >> 2;

    float acc[2][N8][4];
#pragma unroll
    for (int i = 0; i < 2; i++)
#pragma unroll
        for (int j = 0; j < N8; j++)
#pragma unroll
            for (int q = 0; q < 4; q++) acc[i][j][q] = 0.f;

    // ---- prologue: stage 0 ----
    {
        uint32_t base = sb;
#pragma unroll
        for (int i = 0; i < 2; i++) {                 // A: 1024 granules
            int u = tid + i * 512;
            int row = u >> 3, g = u & 7;
            const __half* src = A + (size_t)(mBase + row) * Kpad + g * 8;
            cp16(base + row * 128 + (((g ^ (row & 7)) << 4)), src);
        }
        for (int u = tid; u < NBLK * 8; u += 512) {   // B granules
            int row = u >> 3, g = u & 7;
            const __half* src = B + (size_t)(nBase + row) * Kpad + g * 8;
            cp16(base + ASTAGE + row * 128 + (((g ^ (row & 7)) << 4)), src);
        }
        asm volatile("cp.async.commit_group;" ::: "memory");
    }

    for (int c = 0; c < NC; c++) {
        if (c + 1 < NC) {
            uint32_t base = sb + ((c + 1) & 1) * STAGE;
            int ko = (c + 1) * 64;
#pragma unroll
            for (int i = 0; i < 2; i++) {
                int u = tid + i * 512;
                int row = u >> 3, g = u & 7;
                const __half* src = A + (size_t)(mBase + row) * Kpad + ko + g * 8;
                cp16(base + row * 128 + (((g ^ (row & 7)) << 4)), src);
            }
            for (int u = tid; u < NBLK * 8; u += 512) {
                int row = u >> 3, g = u & 7;
                const __half* src = B + (size_t)(nBase + row) * Kpad + ko + g * 8;
                cp16(base + ASTAGE + row * 128 + (((g ^ (row & 7)) << 4)), src);
            }
            asm volatile("cp.async.commit_group;" ::: "memory");
            asm volatile("cp.async.wait_group 1;" ::: "memory");
        } else {
            asm volatile("cp.async.wait_group 0;" ::: "memory");
        }
        __syncthreads();

        uint32_t aB = sb + (c & 1) * STAGE;
        uint32_t bB = aB + ASTAGE;
#pragma unroll
        for (int k16 = 0; k16 < 4; k16++) {
            int c0 = k16 * 8;
            uint32_t Af[2][4];
#pragma unroll
            for (int mf = 0; mf < 2; mf++) {
                int r0 = warpM * 32 + mf * 16 + lq;
                Af[mf][0] = lds32(smaddr(aB, r0,     c0 + kp));
                Af[mf][1] = lds32(smaddr(aB, r0 + 8, c0 + kp));
                Af[mf][2] = lds32(smaddr(aB, r0,     c0 + kp + 4));
                Af[mf][3] = lds32(smaddr(aB, r0 + 8, c0 + kp + 4));
            }
#pragma unroll
            for (int n8 = 0; n8 < N8; n8++) {
                int n = warpN * N8 * 8 + n8 * 8 + lq;
                uint32_t b0 = lds32(smaddr(bB, n, c0 + kp));
                uint32_t b1 = lds32(smaddr(bB, n, c0 + kp + 4));
#pragma unroll
                for (int mf = 0; mf < 2; mf++)
                    mma_f16(acc[mf][n8], Af[mf][0], Af[mf][1], Af[mf][2], Af[mf][3], b0, b1);
            }
        }
        __syncthreads();
    }

    // ---- epilogue ----
    int limit = nwrite - nBase;
    float s1[2][2] = {{0.f, 0.f}, {0.f, 0.f}};
    float s2[2][2] = {{0.f, 0.f}, {0.f, 0.f}};
#pragma unroll
    for (int mf = 0; mf < 2; mf++) {
        int gr0 = mBase + warpM * 32 + mf * 16 + lq;
#pragma unroll
        for (int n8 = 0; n8 < N8; n8++) {
            int cl = warpN * N8 * 8 + n8 * 8 + kp * 2;
            float v[4];
#pragma unroll
            for (int q = 0; q < 4; q++) v[q] = acc[mf][n8][q];
#pragma unroll
            for (int q = 0; q < 4; q++) {
                int col = cl + (q & 1);
                if (col < limit) {
                    float x = v[q];
                    if (bias) x += bias[nBase + col];
                    if (act) x = x > 0.f ? x : 0.01f * x;
                    v[q] = x;
                }
            }
            if (a_src) {
                s1[mf][0] += v[0] * a_src[cl] + v[1] * a_src[cl + 1];
                s2[mf][0] += v[0] * a_dst[cl] + v[1] * a_dst[cl + 1];
                s1[mf][1] += v[2] * a_src[cl] + v[3] * a_src[cl + 1];
                s2[mf][1] += v[2] * a_dst[cl] + v[3] * a_dst[cl + 1];
            }
            if (outf) {
                if (cl + 1 < limit) {
                    *(float2*)(outf + (size_t)gr0 * ldout + nBase + cl) = make_float2(v[0], v[1]);
                    *(float2*)(outf + (size_t)(gr0 + 8) * ldout + nBase + cl) = make_float2(v[2], v[3]);
                } else if (cl < limit) {
                    outf[(size_t)gr0 * ldout + nBase + cl] = v[0];
                    outf[(size_t)(gr0 + 8) * ldout + nBase + cl] = v[2];
                }
            }
            if (outh && cl < limit) {
                *(__half2*)(outh + (size_t)gr0 * ldout + nBase + cl) = __floats2half2_rn(v[0], v[1]);
                *(__half2*)(outh + (size_t)(gr0 + 8) * ldout + nBase + cl) = __floats2half2_rn(v[2], v[3]);
            }
        }
    }
    if (a_src) {
        // warpN == head (N8 == 8: warp covers 64 cols == one head)
#pragma unroll
        for (int mf = 0; mf < 2; mf++)
#pragma unroll
            for (int hf = 0; hf < 2; hf++) {
                s1[mf][hf] += __shfl_xor_sync(0xFFFFFFFF, s1[mf][hf], 1);
                s1[mf][hf] += __shfl_xor_sync(0xFFFFFFFF, s1[mf][hf], 2);
                s2[mf][hf] += __shfl_xor_sync(0xFFFFFFFF, s2[mf][hf], 1);
                s2[mf][hf] += __shfl_xor_sync(0xFFFFFFFF, s2[mf][hf], 2);
            }
        if ((lane & 3) == 0) {
#pragma unroll
            for (int mf = 0; mf < 2; mf++)
#pragma unroll
                for (int hf = 0; hf < 2; hf++) {
                    int gr = mBase + warpM * 32 + mf * 16 + hf * 8 + lq;
                    als[gr * 4 + warpN] = s1[mf][hf];
                    ald[gr * 4 + warpN] = s2[mf][hf];
                }
        }
    }
}

// ======================= fused GAT aggregation (one warp per dst) ==========
// h is fp16 (L2-resident). Lane l handles channels [8l, 8(l+1)); head = l>>3.
// Gather loop reads per-edge (src, p) from SMEM (uniform broadcast) so the
// 16B h-loads for consecutive edges are independent -> ILP.
__global__ __launch_bounds__(256)
void gat_agg(const int* __restrict__ offs, const int* __restrict__ srcarr,
             const float4* __restrict__ als4, const float4* __restrict__ ald4,
             const __half* __restrict__ h,
             const float* __restrict__ bias, int act,
             __half* __restrict__ out)
{
    __shared__ int    sh_src[8][32];
    __shared__ float4 sh_p[8][32];
    int w = (blockIdx.x * blockDim.x + threadIdx.x) >> 5;
    int ww = (threadIdx.x >> 5);
    int lane = threadIdx.x & 31;
    if (w >= NNODES) return;
    int n = w;
    int head = lane >> 3;
    int beg = offs[n], end = offs[n + 1];
    float4 aldn = ald4[n];
    float4 an = als4[n];
    float4 eself = leaky4_02(make_float4(an.x + aldn.x, an.y + aldn.y,
                                         an.z + aldn.z, an.w + aldn.w));
    // ---- pass 1: segment max ----
    float4 m = eself;
    for (int j = beg + lane; j < end; j += 32) {
        int s = srcarr[j];
        float4 a = als4[s];
        float4 e = leaky4_02(make_float4(a.x + aldn.x, a.y + aldn.y,
                                         a.z + aldn.z, a.w + aldn.w));
        m.x = fmaxf(m.x, e.x); m.y = fmaxf(m.y, e.y);
        m.z = fmaxf(m.z, e.z); m.w = fmaxf(m.w, e.w);
    }
#pragma unroll
    for (int o = 16; o; o >>= 1) {
        m.x = fmaxf(m.x, __shfl_xor_sync(0xFFFFFFFF, m.x, o));
        m.y = fmaxf(m.y, __shfl_xor_sync(0xFFFFFFFF, m.y, o));
        m.z = fmaxf(m.z, __shfl_xor_sync(0xFFFFFFFF, m.z, o));
        m.w = fmaxf(m.w, __shfl_xor_sync(0xFFFFFFFF, m.w, o));
    }
    // ---- pass 2: p, sum, gather-accumulate (one uint4 = 8 halfs per lane) --
    float acc[8] = {0.f, 0.f, 0.f, 0.f, 0.f, 0.f, 0.f, 0.f};
    float4 psum = make_float4(0.f, 0.f, 0.f, 0.f);
    for (int base = beg; base < end; base += 32) {
        int j = base + lane;
        int valid = j < end;
        int s = valid ? srcarr[j] : 0;
        float4 p = make_float4(0.f, 0.f, 0.f, 0.f);
        if (valid) {
            float4 a = als4[s];
            float4 e = leaky4_02(make_float4(a.x + aldn.x, a.y + aldn.y,
                                             a.z + aldn.z, a.w + aldn.w));
            p.x = __expf(e.x - m.x); p.y = __expf(e.y - m.y);
            p.z = __expf(e.z - m.z); p.w = __expf(e.w - m.w);
            psum.x += p.x; psum.y += p.y; psum.z += p.z; psum.w += p.w;
        }
        sh_src[ww][lane] = s;
        sh_p[ww][lane] = p;
        __syncwarp();
        int cnt = end - base; if (cnt > 32) cnt = 32;
#pragma unroll 4
        for (int jj = 0; jj < cnt; jj++) {
            int sj = sh_src[ww][jj];
            float4 pj = sh_p[ww][jj];
            float pv = (head == 0) ? pj.x : (head == 1) ? pj.y : (head == 2) ? pj.z : pj.w;
            uint4 raw = __ldg((const uint4*)(h + (size_t)sj * HC) + lane);
            float2 f0 = __half22float2(*(__half2*)&raw.x);
            float2 f1 = __half22float2(*(__half2*)&raw.y);
            float2 f2 = __half22float2(*(__half2*)&raw.z);
            float2 f3 = __half22float2(*(__half2*)&raw.w);
            acc[0] += pv * f0.x; acc[1] += pv * f0.y;
            acc[2] += pv * f1.x; acc[3] += pv * f1.y;
            acc[4] += pv * f2.x; acc[5] += pv * f2.y;
            acc[6] += pv * f3.x; acc[7] += pv * f3.y;
        }
        __syncwarp();
    }
#pragma unroll
    for (int o = 16; o; o >>= 1) {
        psum.x += __shfl_xor_sync(0xFFFFFFFF, psum.x, o);
        psum.y += __shfl_xor_sync(0xFFFFFFFF, psum.y, o);
        psum.z += __shfl_xor_sync(0xFFFFFFFF, psum.z, o);
        psum.w += __shfl_xor_sync(0xFFFFFFFF, psum.w, o);
    }
    // self loop contribution
    float4 ps;
    ps.x = __expf(eself.x - m.x); ps.y = __expf(eself.y - m.y);
    ps.z = __expf(eself.z - m.z); ps.w = __expf(eself.w - m.w);
    psum.x += ps.x; psum.y += ps.y; psum.z += ps.z; psum.w += ps.w;
    {
        float pv = (head == 0) ? ps.x : (head == 1) ? ps.y : (head == 2) ? ps.z : ps.w;
        uint4 raw = __ldg((const uint4*)(h + (size_t)n * HC) + lane);
        float2 f0 = __half22float2(*(__half2*)&raw.x);
        float2 f1 = __half22float2(*(__half2*)&raw.y);
        float2 f2 = __half22float2(*(__half2*)&raw.z);
        float2 f3 = __half22float2(*(__half2*)&raw.w);
        acc[0] += pv * f0.x; acc[1] += pv * f0.y;
        acc[2] += pv * f1.x; acc[3] += pv * f1.y;
        acc[4] += pv * f2.x; acc[5] += pv * f2.y;
        acc[6] += pv * f3.x; acc[7] += pv * f3.y;
    }
    // ---- epilogue: divide, bias, act, write fp16 ----
    float sH = (head == 0) ? psum.x : (head == 1) ? psum.y : (head == 2) ? psum.z : psum.w;
    float r = 1.f / sH;
    const float4* b4 = (const float4*)bias;   // channels 8l..8l+8 = b4[2l], b4[2l+1]
    float4 bA = b4[lane * 2], bB = b4[lane * 2 + 1];
    float v[8];
    v[0] = acc[0] * r + bA.x; v[1] = acc[1] * r + bA.y;
    v[2] = acc[2] * r + bA.z; v[3] = acc[3] * r + bA.w;
    v[4] = acc[4] * r + bB.x; v[5] = acc[5] * r + bB.y;
    v[6] = acc[6] * r + bB.z; v[7] = acc[7] * r + bB.w;
    if (act) {
#pragma unroll
        for (int q = 0; q < 8; q++) v[q] = v[q] > 0.f ? v[q] : 0.01f * v[q];
    }
    uint4 pack;
    *(__half2*)&pack.x = __floats2half2_rn(v[0], v[1]);
    *(__half2*)&pack.y = __floats2half2_rn(v[2], v[3]);
    *(__half2*)&pack.z = __floats2half2_rn(v[4], v[5]);
    *(__half2*)&pack.w = __floats2half2_rn(v[6], v[7]);
    *((uint4*)(out + (size_t)n * HC) + lane) = pack;
}

// ======================= host orchestration ================================
#define SMEM_N8  (2 * (16384 + 256 * 128))   // 98304
#define SMEM_N4  (2 * (16384 + 128 * 128))   // 65536

extern "C" void kernel_launch(void* const* d_in, const int* in_sizes, int n_in,
                              void* d_out, int out_size)
{
    const float* x    = (const float*)d_in[0];
    const void*  ei   = d_in[1];
    const float* root = (const float*)d_in[2];
    const float* W[3]  = {(const float*)d_in[3], (const float*)d_in[7],  (const float*)d_in[11]};
    const float* aS[3] = {(const float*)d_in[4], (const float*)d_in[8],  (const float*)d_in[12]};
    const float* aD[3] = {(const float*)d_in[5], (const float*)d_in[9],  (const float*)d_in[13]};
    const float* bb[3] = {(const float*)d_in[6], (const float*)d_in[10], (const float*)d_in[14]};
    const float* fc_w = (const float*)d_in[15];
    const float* fc_b = (const float*)d_in[16];
    const float* r_w1 = (const float*)d_in[17];
    const float* r_b1 = (const float*)d_in[18];
    const float* r_w2 = (const float*)d_in[19];
    const float* r_b2 = (const float*)d_in[20];
    const float* r_w3 = (const float*)d_in[21];
    const float* r_b3 = (const float*)d_in[22];

    float *p_als, *p_ald;
    __half *p_h, *p_A, *p_B, *p_rA, *p_r1, *p_r2;
    int *p_off, *p_cur, *p_srcarr, *p_flag;
    cudaGetSymbolAddress((void**)&p_h,   g_h);
    cudaGetSymbolAddress((void**)&p_A,   g_A);
    cudaGetSymbolAddress((void**)&p_als, g_als);
    cudaGetSymbolAddress((void**)&p_ald, g_ald);
    cudaGetSymbolAddress((void**)&p_off, g_off);
    cudaGetSymbolAddress((void**)&p_cur, g_cur);
    cudaGetSymbolAddress((void**)&p_srcarr, g_srcarr);
    cudaGetSymbolAddress((void**)&p_flag, g_is32);
    cudaGetSymbolAddress((void**)&p_B,   g_B);
    cudaGetSymbolAddress((void**)&p_rA,  g_rA);
    cudaGetSymbolAddress((void**)&p_r1,  g_r1);
    cudaGetSymbolAddress((void**)&p_r2,  g_r2);

    static int smem_set = 0;
    if (!smem_set) {
        cudaFuncSetAttribute(gemm_mma<8>, cudaFuncAttributeMaxDynamicSharedMemorySize, SMEM_N8);
        cudaFuncSetAttribute(gemm_mma<4>, cudaFuncAttributeMaxDynamicSharedMemorySize, SMEM_N4);
        smem_set = 1;
    }

    // ---- CSR build (once per call, reused by all 3 layers) ----
    cudaMemsetAsync(p_flag, 0, sizeof(int));
    detect_idx_kernel<<<(NEDGES + 255) / 256, 256>>>((const long long*)ei, p_flag);
    cudaMemsetAsync(p_cur, 0, NNODES * sizeof(int));
    hist_kernel<<<(NEDGES + 255) / 256, 256>>>(ei, p_flag, p_cur);
    scan_kernel<<<1, 1024>>>(p_cur, p_off);
    scatter_kernel<<<(NEDGES + 255) / 256, 256>>>(ei, p_flag, p_cur, p_srcarr);

    // ---- weight conversions (single launch) ----
    {
        ConvTable t;
        auto set = [&](int i, const float* src, int K, int N, int Kpad, int dstOff, int base) {
            t.d[i].src = src; t.d[i].K = K; t.d[i].N = N; t.d[i].Kpad = Kpad;
            t.d[i].dstOff = dstOff; t.d[i].base = base; t.d[i].elems = ((N + (Kpad==64?7:(Kpad-1))) , 0);
        };
        // fill explicitly (elems = Npad*Kpad)
        int base = 0;
        const float* srcs[7] = {W[0], W[1], W[2], fc_w, r_w1, r_w2, r_w3};
        int Ks[7]    = {80, 256, 256, 256, 60, 512, 512};
        int Ns[7]    = {256, 256, 256, 80, 512, 512, 60};
        int Kpads[7] = {128, 256, 256, 256, 64, 512, 512};
        int Npads[7] = {256, 256, 256, 128, 512, 512, 128};
        int offs7[7] = {OFF_W0, OFF_W1, OFF_W2, OFF_FC, OFF_R1, OFF_R2, OFF_R3};
        for (int i = 0; i < 7; i++) {
            t.d[i].src = srcs[i]; t.d[i].K = Ks[i]; t.d[i].N = Ns[i];
            t.d[i].Kpad = Kpads[i]; t.d[i].dstOff = offs7[i];
            t.d[i].base = base; t.d[i].elems = Npads[i] * Kpads[i];
            base += t.d[i].elems;
        }
        t.total = base;
        conv_B_all<<<(t.total + 255) / 256, 256>>>(t, p_B);
    }

    // x -> fp16, K padded 80->128
    conv_A_kernel<<<(NNODES * 128 + 255) / 256, 256>>>(x, p_A, NNODES, 80, 128);

    const int Kpad[3] = {128, 256, 256};
    const __half* Boff[3] = {p_B + OFF_W0, p_B + OFF_W1, p_B + OFF_W2};

    for (int L = 0; L < 3; L++) {
        gemm_mma<8><<<dim3(NNODES / 128, 1), 512, SMEM_N8>>>(
            p_A, Kpad[L], Boff[L],
            nullptr, p_h, 256, 256,
            nullptr, 0, aS[L], aD[L], p_als, p_ald);
        int act = (L < 2) ? 1 : 0;
        gat_agg<<<NNODES / 8, 256>>>(p_off, p_srcarr,
                                     (const float4*)p_als, (const float4*)p_ald,
                                     p_h, bb[L], act, p_A);
    }

    // rot = h @ fc_w + fc_b -> d_out[0 : N*80]  (NBLK=128, only 80 valid)
    float* rot = (float*)d_out;
    gemm_mma<4><<<dim3(NNODES / 128, 1), 512, SMEM_N4>>>(
        p_A, 256, p_B + OFF_FC,
        rot, nullptr, 80, 80,
        fc_b, 0, nullptr, nullptr, nullptr, nullptr);

    // root MLP
    conv_A_kernel<<<(4096 * 64 + 255) / 256, 256>>>(root, p_rA, 4096, 60, 64);
    gemm_mma<8><<<dim3(32, 2), 512, SMEM_N8>>>(
        p_rA, 64, p_B + OFF_R1,
        nullptr, p_r1, 512, 512,
        r_b1, 1, nullptr, nullptr, nullptr, nullptr);
    gemm_mma<8><<<dim3(32, 2), 512, SMEM_N8>>>(
        p_r1, 512, p_B + OFF_R2,
        nullptr, p_r2, 512, 512,
        r_b2, 1, nullptr, nullptr, nullptr, nullptr);
    float* root_out = rot + (size_t)NNODES * 80;
    gemm_mma<4><<<dim3(32, 1), 512, SMEM_N4>>>(
        p_r2, 512, p_B + OFF_R3,
        root_out, nullptr, 60, 60,
        r_b3, 0, nullptr, nullptr, nullptr, nullptr);
}